// round 5
// baseline (speedup 1.0000x reference)
#include <cuda_runtime.h>

// ---------------- problem constants ----------------
#define BATCH 2
#define NQ    4096
#define NPTS  8192
#define DIM   256      // DIN == DIM == 256
#define KNN_K 16
#define KG2   8
#define NB    25       // KNN_K + KG2 + 1 neighbors
#define FLT_BIG 3.402823466e+38f

// ---------------- scratch (device globals; no allocations) ----------------
__device__ float g_kp [BATCH * NPTS * DIM];
__device__ float g_vp [BATCH * NPTS * DIM];
__device__ float g_gk [BATCH * NQ * KG2 * DIM];
__device__ float g_gv [BATCH * NQ * KG2 * DIM];
__device__ float g_qa [BATCH * DIM];
__device__ float g_kgl[BATCH * DIM];
__device__ float g_vgl[BATCH * DIM];
__device__ int   g_knn[BATCH * NQ * KNN_K];
__device__ float g_db [BATCH * NQ * 24 * 4];            // d rows, stride-4
__device__ float g_X  [(size_t)BATCH * NQ * NB * DIM];  // q-k(+pos), later A2
__device__ float g_V  [(size_t)BATCH * NQ * NB * DIM];  // v(+pos)
__device__ float g_A1 [(size_t)BATCH * NQ * NB * DIM];  // gamma hidden

// ---------------- KNN: one thread per query ----------------
__global__ __launch_bounds__(256)
void knn_kernel(const float* __restrict__ xyz_q, const float* __restrict__ xyz) {
    const int b   = blockIdx.y;
    const int q   = blockIdx.x * 256 + threadIdx.x;
    const int tid = threadIdx.x;
    __shared__ float4 sp[1024];

    const size_t qb = (size_t)(b * NQ + q) * 3;
    const float qx = xyz_q[qb + 0], qy = xyz_q[qb + 1], qz = xyz_q[qb + 2];
    const float qq = qx * qx + qy * qy + qz * qz;

    float dist[KNN_K];
    int   idx [KNN_K];
#pragma unroll
    for (int j = 0; j < KNN_K; ++j) { dist[j] = FLT_BIG; idx[j] = 0; }

    for (int t0 = 0; t0 < NPTS; t0 += 1024) {
        __syncthreads();
        for (int i = tid; i < 1024; i += 256) {
            const size_t pb = (size_t)(b * NPTS + t0 + i) * 3;
            float x = xyz[pb + 0], y = xyz[pb + 1], z = xyz[pb + 2];
            sp[i] = make_float4(x, y, z, x * x + y * y + z * z);
        }
        __syncthreads();
#pragma unroll 4
        for (int i = 0; i < 1024; ++i) {
            const float4 P = sp[i];
            const float dot = qx * P.x + qy * P.y + qz * P.z;
            const float d2  = (qq + P.w) - 2.0f * dot;   // matches reference expansion
            if (d2 < dist[KNN_K - 1]) {
                dist[KNN_K - 1] = d2; idx[KNN_K - 1] = t0 + i;
#pragma unroll
                for (int j = KNN_K - 1; j > 0; --j) {
                    if (dist[j] < dist[j - 1]) {
                        float td = dist[j]; dist[j] = dist[j - 1]; dist[j - 1] = td;
                        int   ti = idx[j];  idx[j]  = idx[j - 1];  idx[j - 1]  = ti;
                    }
                }
            }
        }
    }
#pragma unroll
    for (int j = 0; j < KNN_K; ++j)
        g_knn[(size_t)(b * NQ + q) * KNN_K + j] = idx[j];
}

// ---------------- tiny projections: qa / k_global / v_global ----------------
__global__ __launch_bounds__(256)
void proj_small_kernel(const float* __restrict__ lat,
                       const float* __restrict__ w_qs,
                       const float* __restrict__ w_kg,
                       const float* __restrict__ w_vg) {
    const int b = blockIdx.x, t = threadIdx.x;
    __shared__ float ls[DIM];
    ls[t] = lat[b * DIM + t];
    __syncthreads();
    float aq = 0.f, ak = 0.f, av = 0.f;
    for (int i = 0; i < DIM; ++i) {
        const float l = ls[i];
        aq = fmaf(l, w_qs[i * DIM + t], aq);
        ak = fmaf(l, w_kg[i * DIM + t], ak);
        av = fmaf(l, w_vg[i * DIM + t], av);
    }
    g_qa [b * DIM + t] = aq;
    g_kgl[b * DIM + t] = ak;
    g_vgl[b * DIM + t] = av;
}

// ---------------- generic GEMM: C[M x 256] = A[M x 256] @ W[256 x 256] (+bias)(relu) ----------------
#define BM 64
#define BN 64
#define BK 16

#define MICRO_FMA(AS, WS)                                                         \
    do {                                                                          \
        const float4 ra = *(const float4*)&AS[k][ty << 2];                        \
        const float4 rb = *(const float4*)&WS[k][tx << 2];                        \
        acc[0][0]=fmaf(ra.x,rb.x,acc[0][0]); acc[0][1]=fmaf(ra.x,rb.y,acc[0][1]); \
        acc[0][2]=fmaf(ra.x,rb.z,acc[0][2]); acc[0][3]=fmaf(ra.x,rb.w,acc[0][3]); \
        acc[1][0]=fmaf(ra.y,rb.x,acc[1][0]); acc[1][1]=fmaf(ra.y,rb.y,acc[1][1]); \
        acc[1][2]=fmaf(ra.y,rb.z,acc[1][2]); acc[1][3]=fmaf(ra.y,rb.w,acc[1][3]); \
        acc[2][0]=fmaf(ra.z,rb.x,acc[2][0]); acc[2][1]=fmaf(ra.z,rb.y,acc[2][1]); \
        acc[2][2]=fmaf(ra.z,rb.z,acc[2][2]); acc[2][3]=fmaf(ra.z,rb.w,acc[2][3]); \
        acc[3][0]=fmaf(ra.w,rb.x,acc[3][0]); acc[3][1]=fmaf(ra.w,rb.y,acc[3][1]); \
        acc[3][2]=fmaf(ra.w,rb.z,acc[3][2]); acc[3][3]=fmaf(ra.w,rb.w,acc[3][3]); \
    } while (0)

template<bool RELU>
__global__ __launch_bounds__(256)
void gemm_k256(const float* __restrict__ A, const float* __restrict__ W,
               const float* __restrict__ bias, float* __restrict__ C) {
    __shared__ float As[BK][BM];
    __shared__ float Ws[BK][BN];
    const int tid = threadIdx.x;
    const int m0 = blockIdx.y * BM;
    const int n0 = blockIdx.x * BN;
    const int arow = tid >> 2, acol = (tid & 3) << 2;
    const int wrow = tid >> 4, wcol = (tid & 15) << 2;
    const int ty = tid >> 4, tx = tid & 15;

    float acc[4][4] = {};
    const float* Aptr = A + (size_t)(m0 + arow) * 256 + acol;
    const float* Wptr = W + (size_t)wrow * 256 + n0 + wcol;
    float4 pa = *(const float4*)Aptr;
    float4 pw = *(const float4*)Wptr;

    for (int kk = 0; kk < 256; kk += BK) {
        As[acol + 0][arow] = pa.x;
        As[acol + 1][arow] = pa.y;
        As[acol + 2][arow] = pa.z;
        As[acol + 3][arow] = pa.w;
        *(float4*)&Ws[wrow][wcol] = pw;
        __syncthreads();
        if (kk + BK < 256) {
            pa = *(const float4*)(Aptr + kk + BK);
            pw = *(const float4*)(Wptr + (size_t)(kk + BK) * 256);
        }
#pragma unroll
        for (int k = 0; k < BK; ++k) MICRO_FMA(As, Ws);
        __syncthreads();
    }

    float4 bv = make_float4(0.f, 0.f, 0.f, 0.f);
    if (bias) bv = *(const float4*)(bias + n0 + (tx << 2));
#pragma unroll
    for (int i = 0; i < 4; ++i) {
        float4 o;
        o.x = acc[i][0] + bv.x; o.y = acc[i][1] + bv.y;
        o.z = acc[i][2] + bv.z; o.w = acc[i][3] + bv.w;
        if (RELU) {
            o.x = fmaxf(o.x, 0.f); o.y = fmaxf(o.y, 0.f);
            o.z = fmaxf(o.z, 0.f); o.w = fmaxf(o.w, 0.f);
        }
        *(float4*)(C + (size_t)(m0 + (ty << 2) + i) * 256 + n0 + (tx << 2)) = o;
    }
}

// ---------------- assemble X = qa - k, V = v, and d-rows ----------------
__global__ __launch_bounds__(256)
void assemble_kernel(const float* __restrict__ xyz_q,
                     const float* __restrict__ xyz,
                     const float* __restrict__ closest) {
    const int bq = blockIdx.x;          // b*NQ + q
    const int b  = bq >> 12;            // NQ = 4096
    const int t  = threadIdx.x;
    __shared__ float qa_s[DIM];
    __shared__ int   knn_s[KNN_K];
    __shared__ float q3[3];
    qa_s[t] = g_qa[b * DIM + t];
    if (t < KNN_K) knn_s[t] = g_knn[(size_t)bq * KNN_K + t];
    if (t < 3)     q3[t]    = xyz_q[(size_t)bq * 3 + t];
    __syncthreads();

    const size_t xb = (size_t)bq * NB * DIM;
    const float qv = qa_s[t];
#pragma unroll
    for (int j = 0; j < KNN_K; ++j) {
        const int i = knn_s[j];
        const size_t src = (size_t)(b * NPTS + i) * DIM + t;
        g_X[xb + j * DIM + t] = qv - g_kp[src];
        g_V[xb + j * DIM + t] = g_vp[src];
        if (t < 3)
            g_db[(size_t)(bq * 24 + j) * 4 + t] = q3[t] - xyz[(size_t)(b * NPTS + i) * 3 + t];
    }
#pragma unroll
    for (int g = 0; g < KG2; ++g) {
        const size_t src = (size_t)(bq * KG2 + g) * DIM + t;
        g_X[xb + (KNN_K + g) * DIM + t] = qv - g_gk[src];
        g_V[xb + (KNN_K + g) * DIM + t] = g_gv[src];
        if (t < 3)
            g_db[(size_t)(bq * 24 + KNN_K + g) * 4 + t] = q3[t] - closest[(size_t)(bq * KG2 + g) * 3 + t];
    }
    g_X[xb + 24 * DIM + t] = qv - g_kgl[b * DIM + t];
    g_V[xb + 24 * DIM + t] = g_vgl[b * DIM + t];
}

// ---------------- pos GEMM: fused first MLP layer; adds (pos+b2) into X and V ----------------
__global__ __launch_bounds__(256)
void gemm_pos_kernel(const float* __restrict__ W1, const float* __restrict__ b1,
                     const float* __restrict__ W2, const float* __restrict__ b2) {
    __shared__ float As[BK][BM];
    __shared__ float Ws[BK][BN];
    __shared__ float4 sd[BM];
    const int tid = threadIdx.x;
    const int m0 = blockIdx.y * BM;      // M = BATCH*NQ*24 = 196608
    const int n0 = blockIdx.x * BN;
    const int wrow = tid >> 4, wcol = (tid & 15) << 2;
    const int ty = tid >> 4, tx = tid & 15;
    const int arow = tid & 63, kgrp = tid >> 6;   // kgrp warp-uniform

    if (tid < BM) sd[tid] = *(const float4*)&g_db[(size_t)(m0 + tid) * 4];
    float acc[4][4] = {};
    const float* Wptr = W2 + (size_t)wrow * 256 + n0 + wcol;
    float4 pw = *(const float4*)Wptr;
    __syncthreads();
    const float dx = sd[arow].x, dy = sd[arow].y, dz = sd[arow].z;

    for (int kk = 0; kk < 256; kk += BK) {
#pragma unroll
        for (int i = 0; i < 4; ++i) {
            const int kl = (kgrp << 2) + i;
            const int k  = kk + kl;
            float h = fmaf(dx, W1[k], fmaf(dy, W1[256 + k], fmaf(dz, W1[512 + k], b1[k])));
            As[kl][arow] = fmaxf(h, 0.f);
        }
        *(float4*)&Ws[wrow][wcol] = pw;
        __syncthreads();
        if (kk + BK < 256) pw = *(const float4*)(Wptr + (size_t)(kk + BK) * 256);
#pragma unroll
        for (int k = 0; k < BK; ++k) MICRO_FMA(As, Ws);
        __syncthreads();
    }

    const float4 bv = *(const float4*)(b2 + n0 + (tx << 2));
#pragma unroll
    for (int i = 0; i < 4; ++i) {
        const int r = m0 + (ty << 2) + i;
        const int g = (r / 24) * 25 + (r % 24);     // remap into NB=25 row space
        const size_t off = (size_t)g * DIM + n0 + (tx << 2);
        float4 v;
        v.x = acc[i][0] + bv.x; v.y = acc[i][1] + bv.y;
        v.z = acc[i][2] + bv.z; v.w = acc[i][3] + bv.w;
        float4 xo = *(float4*)(g_X + off);
        xo.x += v.x; xo.y += v.y; xo.z += v.z; xo.w += v.w;
        *(float4*)(g_X + off) = xo;
        float4 vo = *(float4*)(g_V + off);
        vo.x += v.x; vo.y += v.y; vo.z += v.z; vo.w += v.w;
        *(float4*)(g_V + off) = vo;
    }
}

// ---------------- final: per-channel softmax over 25 neighbors, dot with V ----------------
__global__ __launch_bounds__(256)
void final_kernel(float* __restrict__ out) {
    const int bq = blockIdx.x;
    const int f  = threadIdx.x;
    const size_t base = (size_t)bq * NB * DIM + f;
    float a[NB];
#pragma unroll
    for (int j = 0; j < NB; ++j) a[j] = g_X[base + j * DIM];
    float m = a[0];
#pragma unroll
    for (int j = 1; j < NB; ++j) m = fmaxf(m, a[j]);
    float s = 0.f, o = 0.f;
#pragma unroll
    for (int j = 0; j < NB; ++j) {
        const float w = expf(a[j] - m);
        s += w;
        o = fmaf(w, g_V[base + j * DIM], o);
    }
    out[(size_t)bq * DIM + f] = o / s;
}

// ---------------- launch ----------------
extern "C" void kernel_launch(void* const* d_in, const int* in_sizes, int n_in,
                              void* d_out, int out_size) {
    const float* xyz_q  = (const float*)d_in[0];
    const float* lat    = (const float*)d_in[1];
    const float* xyz    = (const float*)d_in[2];
    const float* points = (const float*)d_in[3];
    const float* sgf    = (const float*)d_in[4];
    const float* closest= (const float*)d_in[5];
    const float* w_qs   = (const float*)d_in[6];
    const float* w_ks   = (const float*)d_in[7];
    const float* w_vs   = (const float*)d_in[8];
    const float* w_kc   = (const float*)d_in[9];
    const float* w_vc   = (const float*)d_in[10];
    const float* w_kg   = (const float*)d_in[11];
    const float* w_vg   = (const float*)d_in[12];
    const float* dw1    = (const float*)d_in[13];
    const float* db1    = (const float*)d_in[14];
    const float* dw2    = (const float*)d_in[15];
    const float* db2    = (const float*)d_in[16];
    const float* gw1    = (const float*)d_in[17];
    const float* gb1    = (const float*)d_in[18];
    const float* gw2    = (const float*)d_in[19];
    const float* gb2    = (const float*)d_in[20];

    float *kp, *vp, *gk, *gv, *X, *V, *A1;
    cudaGetSymbolAddress((void**)&kp, g_kp);
    cudaGetSymbolAddress((void**)&vp, g_vp);
    cudaGetSymbolAddress((void**)&gk, g_gk);
    cudaGetSymbolAddress((void**)&gv, g_gv);
    cudaGetSymbolAddress((void**)&X,  g_X);
    cudaGetSymbolAddress((void**)&V,  g_V);
    cudaGetSymbolAddress((void**)&A1, g_A1);

    knn_kernel<<<dim3(NQ / 256, BATCH), 256>>>(xyz_q, xyz);

    gemm_k256<false><<<dim3(4, (BATCH * NPTS) / BM), 256>>>(points, w_ks, nullptr, kp);
    gemm_k256<false><<<dim3(4, (BATCH * NPTS) / BM), 256>>>(points, w_vs, nullptr, vp);
    gemm_k256<false><<<dim3(4, (BATCH * NQ * KG2) / BM), 256>>>(sgf, w_kc, nullptr, gk);
    gemm_k256<false><<<dim3(4, (BATCH * NQ * KG2) / BM), 256>>>(sgf, w_vc, nullptr, gv);

    proj_small_kernel<<<BATCH, 256>>>(lat, w_qs, w_kg, w_vg);

    assemble_kernel<<<BATCH * NQ, 256>>>(xyz_q, xyz, closest);

    gemm_pos_kernel<<<dim3(4, (BATCH * NQ * 24) / BM), 256>>>(dw1, db1, dw2, db2);

    gemm_k256<true ><<<dim3(4, (BATCH * NQ * NB) / BM), 256>>>(X,  gw1, gb1, A1);
    gemm_k256<false><<<dim3(4, (BATCH * NQ * NB) / BM), 256>>>(A1, gw2, gb2, X);

    final_kernel<<<BATCH * NQ, 256>>>((float*)d_out);
}

// round 7
// speedup vs baseline: 1.4546x; 1.4546x over previous
#include <cuda_runtime.h>
#include <cuda_bf16.h>
#include <cstdint>

// ---------------- problem constants ----------------
#define BATCH 2
#define NQ    4096
#define NPTS  8192
#define DIM   256
#define KNN_K 16
#define KG2   8
#define NB    25
#define FLT_BIG 3.402823466e+38f

// ---------------- scratch (device globals; no allocations) ----------------
__device__ float g_kp [BATCH * NPTS * DIM];
__device__ float g_vp [BATCH * NPTS * DIM];
__device__ float g_gk [BATCH * NQ * KG2 * DIM];
__device__ float g_gv [BATCH * NQ * KG2 * DIM];
__device__ float g_qa [BATCH * DIM];
__device__ float g_kgl[BATCH * DIM];
__device__ float g_vgl[BATCH * DIM];
__device__ int   g_knn[BATCH * NQ * KNN_K];
__device__ float g_db [BATCH * NQ * 24 * 4];
__device__ float g_X  [(size_t)BATCH * NQ * NB * DIM];
__device__ float g_V  [(size_t)BATCH * NQ * NB * DIM];
__device__ float g_A1 [(size_t)BATCH * NQ * NB * DIM];
// prepacked weights: 7 weights x 8 k-chunks x 2 n-blocks, each region =
// [hi: 128 n-rows x 40 bf16][lo: same] = 20480 B = 1280 uint4
__device__ uint4 g_Bpack[7 * 8 * 2 * 1280];

// ---------------- mma/ldmatrix helpers (portable PTX, no 'a'-gated features) --
#define LDM_X4(r0, r1, r2, r3, addr) \
    asm volatile("ldmatrix.sync.aligned.m8n8.x4.shared.b16 {%0,%1,%2,%3}, [%4];" \
        : "=r"(r0), "=r"(r1), "=r"(r2), "=r"(r3) : "r"(addr))

#define MMA16816(d, a, b) \
    asm volatile("mma.sync.aligned.m16n8k16.row.col.f32.bf16.bf16.f32 " \
        "{%0,%1,%2,%3}, {%4,%5,%6,%7}, {%8,%9}, {%0,%1,%2,%3};" \
        : "+f"((d)[0]), "+f"((d)[1]), "+f"((d)[2]), "+f"((d)[3]) \
        : "r"((a)[0]), "r"((a)[1]), "r"((a)[2]), "r"((a)[3]), \
          "r"((b)[0]), "r"((b)[1]))

__device__ __forceinline__ uint32_t smem_u32(const void* p) {
    uint32_t a;
    asm("{ .reg .u64 t; cvta.to.shared.u64 t, %1; cvt.u32.u64 %0, t; }" : "=r"(a) : "l"(p));
    return a;
}

// two fp32 -> packed bf16 hi pair + lo (residual) pair
__device__ __forceinline__ void split2(float a, float b, uint32_t& h, uint32_t& l) {
    __nv_bfloat16 ha = __float2bfloat16(a), hb = __float2bfloat16(b);
    float ra = a - __bfloat162float(ha);
    float rb = b - __bfloat162float(hb);
    h = (uint32_t)__bfloat16_as_ushort(ha) | ((uint32_t)__bfloat16_as_ushort(hb) << 16);
    __nv_bfloat16 la = __float2bfloat16(ra), lb = __float2bfloat16(rb);
    l = (uint32_t)__bfloat16_as_ushort(la) | ((uint32_t)__bfloat16_as_ushort(lb) << 16);
}

// SMEM stage layout (bytes): [A_hi 10240][A_lo 10240][B_hi 10240][B_lo 10240]
// rows are 40 bf16 = 80 B (padded from 64 B) -> ldmatrix conflict-free
#define STAGE_BYTES 40960
#define OFF_AL 10240
#define OFF_BH 20480
#define OFF_BL 30720
#define SMEM_DYN (2 * STAGE_BYTES)

// ---------------- KNN: one thread per query ----------------
__global__ __launch_bounds__(256)
void knn_kernel(const float* __restrict__ xyz_q, const float* __restrict__ xyz) {
    const int b   = blockIdx.y;
    const int q   = blockIdx.x * 256 + threadIdx.x;
    const int tid = threadIdx.x;
    __shared__ float4 sp[1024];

    const size_t qb = (size_t)(b * NQ + q) * 3;
    const float qx = xyz_q[qb + 0], qy = xyz_q[qb + 1], qz = xyz_q[qb + 2];
    const float qq = qx * qx + qy * qy + qz * qz;

    float dist[KNN_K];
    int   idx [KNN_K];
#pragma unroll
    for (int j = 0; j < KNN_K; ++j) { dist[j] = FLT_BIG; idx[j] = 0; }

    for (int t0 = 0; t0 < NPTS; t0 += 1024) {
        __syncthreads();
        for (int i = tid; i < 1024; i += 256) {
            const size_t pb = (size_t)(b * NPTS + t0 + i) * 3;
            float x = xyz[pb + 0], y = xyz[pb + 1], z = xyz[pb + 2];
            sp[i] = make_float4(x, y, z, x * x + y * y + z * z);
        }
        __syncthreads();
#pragma unroll 4
        for (int i = 0; i < 1024; ++i) {
            const float4 P = sp[i];
            const float dot = qx * P.x + qy * P.y + qz * P.z;
            const float d2  = (qq + P.w) - 2.0f * dot;
            if (d2 < dist[KNN_K - 1]) {
                dist[KNN_K - 1] = d2; idx[KNN_K - 1] = t0 + i;
#pragma unroll
                for (int j = KNN_K - 1; j > 0; --j) {
                    if (dist[j] < dist[j - 1]) {
                        float td = dist[j]; dist[j] = dist[j - 1]; dist[j - 1] = td;
                        int   ti = idx[j];  idx[j]  = idx[j - 1];  idx[j - 1]  = ti;
                    }
                }
            }
        }
    }
#pragma unroll
    for (int j = 0; j < KNN_K; ++j)
        g_knn[(size_t)(b * NQ + q) * KNN_K + j] = idx[j];
}

// ---------------- tiny projections ----------------
__global__ __launch_bounds__(256)
void proj_small_kernel(const float* __restrict__ lat,
                       const float* __restrict__ w_qs,
                       const float* __restrict__ w_kg,
                       const float* __restrict__ w_vg) {
    const int b = blockIdx.x, t = threadIdx.x;
    __shared__ float ls[DIM];
    ls[t] = lat[b * DIM + t];
    __syncthreads();
    float aq = 0.f, ak = 0.f, av = 0.f;
    for (int i = 0; i < DIM; ++i) {
        const float l = ls[i];
        aq = fmaf(l, w_qs[i * DIM + t], aq);
        ak = fmaf(l, w_kg[i * DIM + t], ak);
        av = fmaf(l, w_vg[i * DIM + t], av);
    }
    g_qa [b * DIM + t] = aq;
    g_kgl[b * DIM + t] = ak;
    g_vgl[b * DIM + t] = av;
}

// ---------------- weight prepack: W[k][n] -> per-(w,kc,nblk) region ----------------
// region = [hi 128 rows(n) x 40 bf16][lo same]; row stride 40 bf16 (80 B)
// bid = ((w*8 + kc)*2 + nblk)
__global__ __launch_bounds__(256)
void prepack_kernel(const float* __restrict__ w0, const float* __restrict__ w1,
                    const float* __restrict__ w2, const float* __restrict__ w3,
                    const float* __restrict__ w4, const float* __restrict__ w5,
                    const float* __restrict__ w6) {
    const float* Ws[7] = {w0, w1, w2, w3, w4, w5, w6};
    const int bid = blockIdx.x;
    const int w = bid >> 4, kc = (bid >> 1) & 7, nblk = bid & 1;
    const float* W = Ws[w];
    char* dst = (char*)g_Bpack + (size_t)bid * 20480;
#pragma unroll
    for (int i = 0; i < 16; ++i) {
        const int idx = threadIdx.x + i * 256;         // 0..4095
        const int n_local = idx >> 5, k_local = idx & 31;
        const int n = nblk * 128 + n_local;
        const int k = kc * 32 + k_local;
        const float x = W[(size_t)k * 256 + n];
        __nv_bfloat16 h = __float2bfloat16(x);
        float lo = x - __bfloat162float(h);
        *(__nv_bfloat16*)(dst + n_local * 80 + k_local * 2)         = h;
        *(__nv_bfloat16*)(dst + 10240 + n_local * 80 + k_local * 2) = __float2bfloat16(lo);
    }
}

// ---------------- mma.sync GEMM: C[M x 256] = A[M x 256] @ W[256 x 256] (bf16x3) ----
// AMODE 0: A from gmem fp32.  AMODE 1: A = relu(d @ W1 + b1) from g_db.
// EPI 0: C = acc (+bias).  EPI 1: +relu.  EPI 2: accumulate into g_X/g_V (24->25 remap).
template<int AMODE, int EPI>
__global__ __launch_bounds__(256, 1)
void gemm_mma_kernel(const float* __restrict__ A, int widx,
                     const float* __restrict__ bias, float* __restrict__ C,
                     const float* __restrict__ W1, const float* __restrict__ b1) {
    extern __shared__ char smem_dyn[];
    const uint32_t sbase = smem_u32(smem_dyn);
    const int tid = threadIdx.x, lane = tid & 31, wid = tid >> 5;
    const int warp_m = wid & 3, warp_n = wid >> 2;
    const int m0 = blockIdx.x * 128;
    const int n0 = blockIdx.y * 128;

    const int arow  = tid >> 1;              // A producer: row 0..127
    const int khalf = (tid & 1) * 16;        // k half within 32-chunk

    // B pack regions for this n-block: region idx = (widx*8 + kc)*2 + nblk
    const uint4* bpack = g_Bpack + ((size_t)(widx * 8) * 2 + blockIdx.y) * 1280;

    float acc[2][8][4];
#pragma unroll
    for (int mt = 0; mt < 2; ++mt)
#pragma unroll
        for (int nt = 0; nt < 8; ++nt)
#pragma unroll
            for (int j = 0; j < 4; ++j) acc[mt][nt][j] = 0.f;

    // ---- prologue: prefetch chunk 0 ----
    uint4 bpre[5];
#pragma unroll
    for (int i = 0; i < 5; ++i) bpre[i] = bpack[tid + i * 256];
    float4 a4[4];
    if (AMODE == 0) {
        const float4* ap = (const float4*)(A + (size_t)(m0 + arow) * 256 + khalf);
#pragma unroll
        for (int i = 0; i < 4; ++i) a4[i] = ap[i];
    }

    for (int c = 0; c < 8; ++c) {
        char* stc = smem_dyn + (c & 1) * STAGE_BYTES;
        const uint32_t sb = sbase + (c & 1) * STAGE_BYTES;

        // ---- store B (prepacked, contiguous copy) ----
        {
            uint4* bs = (uint4*)(stc + OFF_BH);   // [hi 10240][lo 10240] contiguous
#pragma unroll
            for (int i = 0; i < 5; ++i) bs[tid + i * 256] = bpre[i];
        }
        // ---- produce + store A tile (bf16 hi/lo split) ----
        {
            float v[16];
            if (AMODE == 0) {
#pragma unroll
                for (int i = 0; i < 4; ++i) {
                    v[i * 4 + 0] = a4[i].x; v[i * 4 + 1] = a4[i].y;
                    v[i * 4 + 2] = a4[i].z; v[i * 4 + 3] = a4[i].w;
                }
            } else {
                const float4 dd = *(const float4*)(g_db + (size_t)(m0 + arow) * 4);
#pragma unroll
                for (int i = 0; i < 16; ++i) {
                    const int k = c * 32 + khalf + i;
                    float h = fmaf(dd.x, W1[k], fmaf(dd.y, W1[256 + k], fmaf(dd.z, W1[512 + k], b1[k])));
                    v[i] = fmaxf(h, 0.f);
                }
            }
            uint4 h0, l0, h1, l1;
            split2(v[0],  v[1],  h0.x, l0.x); split2(v[2],  v[3],  h0.y, l0.y);
            split2(v[4],  v[5],  h0.z, l0.z); split2(v[6],  v[7],  h0.w, l0.w);
            split2(v[8],  v[9],  h1.x, l1.x); split2(v[10], v[11], h1.y, l1.y);
            split2(v[12], v[13], h1.z, l1.z); split2(v[14], v[15], h1.w, l1.w);
            const int ab = arow * 80 + khalf * 2;
            *(uint4*)(stc + ab)               = h0;
            *(uint4*)(stc + ab + 16)          = h1;
            *(uint4*)(stc + OFF_AL + ab)      = l0;
            *(uint4*)(stc + OFF_AL + ab + 16) = l1;
        }
        __syncthreads();

        // ---- prefetch chunk c+1 while computing on chunk c ----
        if (c < 7) {
            const uint4* bp2 = bpack + (size_t)(c + 1) * 2 * 1280;
#pragma unroll
            for (int i = 0; i < 5; ++i) bpre[i] = bp2[tid + i * 256];
            if (AMODE == 0) {
                const float4* ap = (const float4*)(A + (size_t)(m0 + arow) * 256 + (c + 1) * 32 + khalf);
#pragma unroll
                for (int i = 0; i < 4; ++i) a4[i] = ap[i];
            }
        }

        // ---- mma over this chunk: 2 k16 steps x 3 split terms ----
#pragma unroll
        for (int ks = 0; ks < 2; ++ks) {
            uint32_t ah[2][4], al[2][4];
#pragma unroll
            for (int mt = 0; mt < 2; ++mt) {
                const uint32_t ra = sb + (uint32_t)(warp_m * 32 + mt * 16 + (lane & 15)) * 80
                                  + ks * 32 + ((lane >> 4) << 4);
                LDM_X4(ah[mt][0], ah[mt][1], ah[mt][2], ah[mt][3], ra);
                LDM_X4(al[mt][0], al[mt][1], al[mt][2], al[mt][3], ra + OFF_AL);
            }
            uint32_t bh[8][2], bl[8][2];
#pragma unroll
            for (int np = 0; np < 4; ++np) {
                const uint32_t rb = sb + OFF_BH
                                  + (uint32_t)(warp_n * 64 + np * 16 + (lane & 7) + ((lane >> 4) << 3)) * 80
                                  + ks * 32 + ((lane & 8) ? 16 : 0);
                LDM_X4(bh[2 * np][0], bh[2 * np][1], bh[2 * np + 1][0], bh[2 * np + 1][1], rb);
                LDM_X4(bl[2 * np][0], bl[2 * np][1], bl[2 * np + 1][0], bl[2 * np + 1][1], rb + 10240);
            }
#pragma unroll
            for (int mt = 0; mt < 2; ++mt)
#pragma unroll
                for (int nt = 0; nt < 8; ++nt) {
                    MMA16816(acc[mt][nt], ah[mt], bh[nt]);
                    MMA16816(acc[mt][nt], ah[mt], bl[nt]);
                    MMA16816(acc[mt][nt], al[mt], bh[nt]);
                }
        }
    }

    // ---- epilogue ----
    const int r_base = m0 + warp_m * 32 + (lane >> 2);
    const int c_base = n0 + warp_n * 64 + (lane & 3) * 2;
#pragma unroll
    for (int mt = 0; mt < 2; ++mt) {
#pragma unroll
        for (int half = 0; half < 2; ++half) {
            const int row = r_base + mt * 16 + half * 8;
            float *xp = nullptr, *vp = nullptr;
            if (EPI == 2) {
                const size_t g = ((size_t)row / 24) * 25 + (row % 24);
                xp = g_X + g * 256;
                vp = g_V + g * 256;
            }
#pragma unroll
            for (int nt = 0; nt < 8; ++nt) {
                const int col = c_base + nt * 8;
                float ox = acc[mt][nt][half * 2 + 0];
                float oy = acc[mt][nt][half * 2 + 1];
                if (bias) {
                    const float2 bv = *(const float2*)(bias + col);
                    ox += bv.x; oy += bv.y;
                }
                if (EPI == 1) { ox = fmaxf(ox, 0.f); oy = fmaxf(oy, 0.f); }
                if (EPI == 2) {
                    float2 xo = *(float2*)(xp + col);
                    xo.x += ox; xo.y += oy;
                    *(float2*)(xp + col) = xo;
                    float2 vo = *(float2*)(vp + col);
                    vo.x += ox; vo.y += oy;
                    *(float2*)(vp + col) = vo;
                } else {
                    *(float2*)(C + (size_t)row * 256 + col) = make_float2(ox, oy);
                }
            }
        }
    }
}

// ---------------- assemble X = qa - k, V = v, and d-rows ----------------
__global__ __launch_bounds__(256)
void assemble_kernel(const float* __restrict__ xyz_q,
                     const float* __restrict__ xyz,
                     const float* __restrict__ closest) {
    const int bq = blockIdx.x;
    const int b  = bq >> 12;
    const int t  = threadIdx.x;
    __shared__ float qa_s[DIM];
    __shared__ int   knn_s[KNN_K];
    __shared__ float q3[3];
    qa_s[t] = g_qa[b * DIM + t];
    if (t < KNN_K) knn_s[t] = g_knn[(size_t)bq * KNN_K + t];
    if (t < 3)     q3[t]    = xyz_q[(size_t)bq * 3 + t];
    __syncthreads();

    const size_t xb = (size_t)bq * NB * DIM;
    const float qv = qa_s[t];
#pragma unroll
    for (int j = 0; j < KNN_K; ++j) {
        const int i = knn_s[j];
        const size_t src = (size_t)(b * NPTS + i) * DIM + t;
        g_X[xb + j * DIM + t] = qv - g_kp[src];
        g_V[xb + j * DIM + t] = g_vp[src];
        if (t < 3)
            g_db[(size_t)(bq * 24 + j) * 4 + t] = q3[t] - xyz[(size_t)(b * NPTS + i) * 3 + t];
    }
#pragma unroll
    for (int g = 0; g < KG2; ++g) {
        const size_t src = (size_t)(bq * KG2 + g) * DIM + t;
        g_X[xb + (KNN_K + g) * DIM + t] = qv - g_gk[src];
        g_V[xb + (KNN_K + g) * DIM + t] = g_gv[src];
        if (t < 3)
            g_db[(size_t)(bq * 24 + KNN_K + g) * 4 + t] = q3[t] - closest[(size_t)(bq * KG2 + g) * 3 + t];
    }
    g_X[xb + 24 * DIM + t] = qv - g_kgl[b * DIM + t];
    g_V[xb + 24 * DIM + t] = g_vgl[b * DIM + t];
}

// ---------------- final: per-channel softmax over 25 neighbors, dot with V ------
__global__ __launch_bounds__(256)
void final_kernel(float* __restrict__ out) {
    const int bq = blockIdx.x;
    const int f  = threadIdx.x;
    const size_t base = (size_t)bq * NB * DIM + f;
    float a[NB];
#pragma unroll
    for (int j = 0; j < NB; ++j) a[j] = g_X[base + j * DIM];
    float m = a[0];
#pragma unroll
    for (int j = 1; j < NB; ++j) m = fmaxf(m, a[j]);
    float s = 0.f, o = 0.f;
#pragma unroll
    for (int j = 0; j < NB; ++j) {
        const float w = expf(a[j] - m);
        s += w;
        o = fmaf(w, g_V[base + j * DIM], o);
    }
    out[(size_t)bq * DIM + f] = o / s;
}

// ---------------- launch ----------------
extern "C" void kernel_launch(void* const* d_in, const int* in_sizes, int n_in,
                              void* d_out, int out_size) {
    const float* xyz_q  = (const float*)d_in[0];
    const float* lat    = (const float*)d_in[1];
    const float* xyz    = (const float*)d_in[2];
    const float* points = (const float*)d_in[3];
    const float* sgf    = (const float*)d_in[4];
    const float* closest= (const float*)d_in[5];
    const float* w_qs   = (const float*)d_in[6];
    const float* w_ks   = (const float*)d_in[7];
    const float* w_vs   = (const float*)d_in[8];
    const float* w_kc   = (const float*)d_in[9];
    const float* w_vc   = (const float*)d_in[10];
    const float* w_kg   = (const float*)d_in[11];
    const float* w_vg   = (const float*)d_in[12];
    const float* dw1    = (const float*)d_in[13];
    const float* db1    = (const float*)d_in[14];
    const float* dw2    = (const float*)d_in[15];
    const float* db2    = (const float*)d_in[16];
    const float* gw1    = (const float*)d_in[17];
    const float* gb1    = (const float*)d_in[18];
    const float* gw2    = (const float*)d_in[19];
    const float* gb2    = (const float*)d_in[20];

    float *kp, *vp, *gk, *gv, *X, *A1;
    cudaGetSymbolAddress((void**)&kp, g_kp);
    cudaGetSymbolAddress((void**)&vp, g_vp);
    cudaGetSymbolAddress((void**)&gk, g_gk);
    cudaGetSymbolAddress((void**)&gv, g_gv);
    cudaGetSymbolAddress((void**)&X,  g_X);
    cudaGetSymbolAddress((void**)&A1, g_A1);

    cudaFuncSetAttribute(gemm_mma_kernel<0, 0>, cudaFuncAttributeMaxDynamicSharedMemorySize, SMEM_DYN);
    cudaFuncSetAttribute(gemm_mma_kernel<0, 1>, cudaFuncAttributeMaxDynamicSharedMemorySize, SMEM_DYN);
    cudaFuncSetAttribute(gemm_mma_kernel<1, 2>, cudaFuncAttributeMaxDynamicSharedMemorySize, SMEM_DYN);

    // weight pack order: 0=w_ks 1=w_vs 2=w_kc 3=w_vc 4=dw2 5=gw1 6=gw2
    prepack_kernel<<<112, 256>>>(w_ks, w_vs, w_kc, w_vc, dw2, gw1, gw2);

    knn_kernel<<<dim3(NQ / 256, BATCH), 256>>>(xyz_q, xyz);

    gemm_mma_kernel<0, 0><<<dim3((BATCH * NPTS) / 128, 2), 256, SMEM_DYN>>>(points, 0, nullptr, kp, nullptr, nullptr);
    gemm_mma_kernel<0, 0><<<dim3((BATCH * NPTS) / 128, 2), 256, SMEM_DYN>>>(points, 1, nullptr, vp, nullptr, nullptr);
    gemm_mma_kernel<0, 0><<<dim3((BATCH * NQ * KG2) / 128, 2), 256, SMEM_DYN>>>(sgf, 2, nullptr, gk, nullptr, nullptr);
    gemm_mma_kernel<0, 0><<<dim3((BATCH * NQ * KG2) / 128, 2), 256, SMEM_DYN>>>(sgf, 3, nullptr, gv, nullptr, nullptr);

    proj_small_kernel<<<BATCH, 256>>>(lat, w_qs, w_kg, w_vg);

    assemble_kernel<<<BATCH * NQ, 256>>>(xyz_q, xyz, closest);

    // pos layer2 (layer1 fused into A producer); epilogue accumulates into X and V
    gemm_mma_kernel<1, 2><<<dim3((BATCH * NQ * 24) / 128, 2), 256, SMEM_DYN>>>(nullptr, 4, db2, nullptr, dw1, db1);

    // gamma MLP
    gemm_mma_kernel<0, 1><<<dim3((BATCH * NQ * NB) / 128, 2), 256, SMEM_DYN>>>(X,  5, gb1, A1, nullptr, nullptr);
    gemm_mma_kernel<0, 0><<<dim3((BATCH * NQ * NB) / 128, 2), 256, SMEM_DYN>>>(A1, 6, gb2, X,  nullptr, nullptr);

    final_kernel<<<BATCH * NQ, 256>>>((float*)d_out);
}

// round 10
// speedup vs baseline: 1.5175x; 1.0433x over previous
#include <cuda_runtime.h>
#include <cuda_bf16.h>
#include <cstdint>

// ---------------- problem constants ----------------
#define BATCH 2
#define NQ    4096
#define NPTS  8192
#define DIM   256
#define KNN_K 16
#define KG2   8
#define NB    25
#define FLT_BIG 3.402823466e+38f

// ---------------- scratch (device globals; no allocations) ----------------
__device__ float g_kp [BATCH * NPTS * DIM];
__device__ float g_vp [BATCH * NPTS * DIM];
__device__ float g_gk [BATCH * NQ * KG2 * DIM];
__device__ float g_gv [BATCH * NQ * KG2 * DIM];
__device__ float g_qa [BATCH * DIM];
__device__ float g_kgl[BATCH * DIM];
__device__ float g_vgl[BATCH * DIM];
__device__ int   g_knn[BATCH * NQ * KNN_K];
__device__ float g_db [BATCH * NQ * 24 * 4];
__device__ float g_X  [(size_t)BATCH * NQ * NB * DIM];
__device__ float g_V  [(size_t)BATCH * NQ * NB * DIM];
__device__ float g_A1 [(size_t)BATCH * NQ * NB * DIM];
// prepacked weights: 7 weights x 8 k-chunks x 2 n-blocks, each region =
// [hi: 128 n-rows x 40 bf16][lo: same] = 20480 B = 1280 uint4
__device__ uint4 g_Bpack[7 * 8 * 2 * 1280];

// ---------------- mma/ldmatrix helpers (portable PTX, no 'a'-gated features) --
#define LDM_X4(r0, r1, r2, r3, addr) \
    asm volatile("ldmatrix.sync.aligned.m8n8.x4.shared.b16 {%0,%1,%2,%3}, [%4];" \
        : "=r"(r0), "=r"(r1), "=r"(r2), "=r"(r3) : "r"(addr))

#define MMA16816(d, a, b) \
    asm volatile("mma.sync.aligned.m16n8k16.row.col.f32.bf16.bf16.f32 " \
        "{%0,%1,%2,%3}, {%4,%5,%6,%7}, {%8,%9}, {%0,%1,%2,%3};" \
        : "+f"((d)[0]), "+f"((d)[1]), "+f"((d)[2]), "+f"((d)[3]) \
        : "r"((a)[0]), "r"((a)[1]), "r"((a)[2]), "r"((a)[3]), \
          "r"((b)[0]), "r"((b)[1]))

__device__ __forceinline__ uint32_t smem_u32(const void* p) {
    uint32_t a;
    asm("{ .reg .u64 t; cvta.to.shared.u64 t, %1; cvt.u32.u64 %0, t; }" : "=r"(a) : "l"(p));
    return a;
}

// two fp32 -> packed bf16 hi pair + lo (residual) pair
__device__ __forceinline__ void split2(float a, float b, uint32_t& h, uint32_t& l) {
    __nv_bfloat16 ha = __float2bfloat16(a), hb = __float2bfloat16(b);
    float ra = a - __bfloat162float(ha);
    float rb = b - __bfloat162float(hb);
    h = (uint32_t)__bfloat16_as_ushort(ha) | ((uint32_t)__bfloat16_as_ushort(hb) << 16);
    __nv_bfloat16 la = __float2bfloat16(ra), lb = __float2bfloat16(rb);
    l = (uint32_t)__bfloat16_as_ushort(la) | ((uint32_t)__bfloat16_as_ushort(lb) << 16);
}

// SMEM stage layout (bytes): [A_hi 5120][A_lo 5120][B_hi 10240][B_lo 10240]
// rows are 40 bf16 = 80 B (padded from 64 B) -> ldmatrix conflict-free
#define STAGE_BYTES 30720
#define OFF_AL 5120
#define OFF_BH 10240
#define SMEM_DYN (2 * STAGE_BYTES)

// ---------------- KNN: 64 queries x 4 point-chunks per block ----------------
__global__ __launch_bounds__(256)
void knn_kernel(const float* __restrict__ xyz_q, const float* __restrict__ xyz) {
    const int b      = blockIdx.y;
    const int tid    = threadIdx.x;
    const int qlocal = tid & 63;
    const int chunk  = tid >> 6;
    const int q      = blockIdx.x * 64 + qlocal;

    __shared__ float4 sp[1024];
    __shared__ float  sd[4][64][KNN_K];
    __shared__ int    si[4][64][KNN_K];

    const size_t qb = (size_t)(b * NQ + q) * 3;
    const float qx = xyz_q[qb + 0], qy = xyz_q[qb + 1], qz = xyz_q[qb + 2];
    const float qq = qx * qx + qy * qy + qz * qz;

    float dist[KNN_K];
    int   idx [KNN_K];
#pragma unroll
    for (int j = 0; j < KNN_K; ++j) { dist[j] = FLT_BIG; idx[j] = 0; }

    for (int tile = 0; tile < 8; ++tile) {
        const int t0 = tile * 1024;
        __syncthreads();
        for (int i = tid; i < 1024; i += 256) {
            const size_t pb = (size_t)(b * NPTS + t0 + i) * 3;
            float x = xyz[pb + 0], y = xyz[pb + 1], z = xyz[pb + 2];
            sp[i] = make_float4(x, y, z, x * x + y * y + z * z);
        }
        __syncthreads();
        if ((tile & 3) != chunk) continue;
#pragma unroll 4
        for (int i = 0; i < 1024; ++i) {
            const float4 P = sp[i];
            const float dot = qx * P.x + qy * P.y + qz * P.z;
            const float d2  = (qq + P.w) - 2.0f * dot;
            if (d2 < dist[KNN_K - 1]) {
                dist[KNN_K - 1] = d2; idx[KNN_K - 1] = t0 + i;
#pragma unroll
                for (int j = KNN_K - 1; j > 0; --j) {
                    if (dist[j] < dist[j - 1]) {
                        float td = dist[j]; dist[j] = dist[j - 1]; dist[j - 1] = td;
                        int   ti = idx[j];  idx[j]  = idx[j - 1];  idx[j - 1]  = ti;
                    }
                }
            }
        }
    }
#pragma unroll
    for (int j = 0; j < KNN_K; ++j) {
        sd[chunk][qlocal][j] = dist[j];
        si[chunk][qlocal][j] = idx[j];
    }
    __syncthreads();
    if (tid < 64) {
        const int qg = blockIdx.x * 64 + tid;
        int p0 = 0, p1 = 0, p2 = 0, p3 = 0;
#pragma unroll
        for (int j = 0; j < KNN_K; ++j) {
            const float v0 = (p0 < KNN_K) ? sd[0][tid][p0] : FLT_BIG;
            const float v1 = (p1 < KNN_K) ? sd[1][tid][p1] : FLT_BIG;
            const float v2 = (p2 < KNN_K) ? sd[2][tid][p2] : FLT_BIG;
            const float v3 = (p3 < KNN_K) ? sd[3][tid][p3] : FLT_BIG;
            int best;
            float m01 = fminf(v0, v1), m23 = fminf(v2, v3);
            if (fminf(m01, m23) == v0)      best = 0;
            else if (m01 <= m23)            best = 1;
            else if (m23 == v2)             best = 2;
            else                            best = 3;
            int pick;
            if      (best == 0) { pick = si[0][tid][p0]; ++p0; }
            else if (best == 1) { pick = si[1][tid][p1]; ++p1; }
            else if (best == 2) { pick = si[2][tid][p2]; ++p2; }
            else                { pick = si[3][tid][p3]; ++p3; }
            g_knn[(size_t)(b * NQ + qg) * KNN_K + j] = pick;
        }
    }
}

// ---------------- tiny projections ----------------
__global__ __launch_bounds__(256)
void proj_small_kernel(const float* __restrict__ lat,
                       const float* __restrict__ w_qs,
                       const float* __restrict__ w_kg,
                       const float* __restrict__ w_vg) {
    const int b = blockIdx.x, t = threadIdx.x;
    __shared__ float ls[DIM];
    ls[t] = lat[b * DIM + t];
    __syncthreads();
    float aq = 0.f, ak = 0.f, av = 0.f;
    for (int i = 0; i < DIM; ++i) {
        const float l = ls[i];
        aq = fmaf(l, w_qs[i * DIM + t], aq);
        ak = fmaf(l, w_kg[i * DIM + t], ak);
        av = fmaf(l, w_vg[i * DIM + t], av);
    }
    g_qa [b * DIM + t] = aq;
    g_kgl[b * DIM + t] = ak;
    g_vgl[b * DIM + t] = av;
}

// ---------------- weight prepack: W[k][n] -> per-(w,kc,nblk) region ----------------
// region = [hi 128 rows(n) x 40 bf16][lo same]; row stride 40 bf16 (80 B)
// bid = ((w*8 + kc)*2 + nblk)
__global__ __launch_bounds__(256)
void prepack_kernel(const float* __restrict__ w0, const float* __restrict__ w1,
                    const float* __restrict__ w2, const float* __restrict__ w3,
                    const float* __restrict__ w4, const float* __restrict__ w5,
                    const float* __restrict__ w6) {
    const float* Ws[7] = {w0, w1, w2, w3, w4, w5, w6};
    const int bid = blockIdx.x;
    const int w = bid >> 4, kc = (bid >> 1) & 7, nblk = bid & 1;
    const float* W = Ws[w];
    char* dst = (char*)g_Bpack + (size_t)bid * 20480;
#pragma unroll
    for (int i = 0; i < 16; ++i) {
        const int idx = threadIdx.x + i * 256;         // 0..4095
        const int n_local = idx >> 5, k_local = idx & 31;
        const int n = nblk * 128 + n_local;
        const int k = kc * 32 + k_local;
        const float x = W[(size_t)k * 256 + n];
        __nv_bfloat16 h = __float2bfloat16(x);
        float lo = x - __bfloat162float(h);
        *(__nv_bfloat16*)(dst + n_local * 80 + k_local * 2)         = h;
        *(__nv_bfloat16*)(dst + 10240 + n_local * 80 + k_local * 2) = __float2bfloat16(lo);
    }
}

// ---------------- mma.sync GEMM: C[M x 256] = A[M x 256] @ W[256 x 256] (bf16x3) ----
// CTA tile M64 x N128; 8 warps as 2(m) x 4(n), warp tile 32x32.
// AMODE 0: A from gmem fp32.  AMODE 1: A = relu(d @ W1 + b1) from g_db.
// EPI 0: C = acc (+bias).  EPI 1: +relu.  EPI 2: accumulate into g_X/g_V (24->25 remap).
template<int AMODE, int EPI>
__global__ __launch_bounds__(256, 2)
void gemm_mma_kernel(const float* __restrict__ A, int widx,
                     const float* __restrict__ bias, float* __restrict__ C,
                     const float* __restrict__ W1, const float* __restrict__ b1) {
    extern __shared__ char smem_dyn[];
    const uint32_t sbase = smem_u32(smem_dyn);
    const int tid = threadIdx.x, lane = tid & 31, wid = tid >> 5;
    const int warp_n = wid & 3, warp_m = wid >> 2;
    const int m0 = blockIdx.x * 64;
    const int n0 = blockIdx.y * 128;

    const int arow = tid >> 2;               // A producer: row 0..63
    const int kq   = (tid & 3) * 8;          // k-eighth within 32-chunk

    // B pack regions for this n-block: region idx = (widx*8 + kc)*2 + nblk
    const uint4* bpack = g_Bpack + ((size_t)(widx * 8) * 2 + blockIdx.y) * 1280;

    float acc[2][4][4];
#pragma unroll
    for (int mt = 0; mt < 2; ++mt)
#pragma unroll
        for (int nt = 0; nt < 4; ++nt)
#pragma unroll
            for (int j = 0; j < 4; ++j) acc[mt][nt][j] = 0.f;

    // ---- prologue: prefetch chunk 0 ----
    uint4 bpre[5];
#pragma unroll
    for (int i = 0; i < 5; ++i) bpre[i] = bpack[tid + i * 256];
    float4 a4[2];
    if (AMODE == 0) {
        const float4* ap = (const float4*)(A + (size_t)(m0 + arow) * 256 + kq);
        a4[0] = ap[0]; a4[1] = ap[1];
    }

    for (int c = 0; c < 8; ++c) {
        char* stc = smem_dyn + (c & 1) * STAGE_BYTES;
        const uint32_t sb = sbase + (c & 1) * STAGE_BYTES;

        // ---- store B (prepacked, contiguous copy: [hi 10240][lo 10240]) ----
        {
            uint4* bs = (uint4*)(stc + OFF_BH);
#pragma unroll
            for (int i = 0; i < 5; ++i) bs[tid + i * 256] = bpre[i];
        }
        // ---- produce + store A tile (bf16 hi/lo split) ----
        {
            float v[8];
            if (AMODE == 0) {
                v[0] = a4[0].x; v[1] = a4[0].y; v[2] = a4[0].z; v[3] = a4[0].w;
                v[4] = a4[1].x; v[5] = a4[1].y; v[6] = a4[1].z; v[7] = a4[1].w;
            } else {
                const float4 dd = *(const float4*)(g_db + (size_t)(m0 + arow) * 4);
#pragma unroll
                for (int i = 0; i < 8; ++i) {
                    const int k = c * 32 + kq + i;
                    float h = fmaf(dd.x, W1[k], fmaf(dd.y, W1[256 + k], fmaf(dd.z, W1[512 + k], b1[k])));
                    v[i] = fmaxf(h, 0.f);
                }
            }
            uint4 h0, l0;
            split2(v[0], v[1], h0.x, l0.x); split2(v[2], v[3], h0.y, l0.y);
            split2(v[4], v[5], h0.z, l0.z); split2(v[6], v[7], h0.w, l0.w);
            const int ab = arow * 80 + kq * 2;
            *(uint4*)(stc + ab)          = h0;
            *(uint4*)(stc + OFF_AL + ab) = l0;
        }
        __syncthreads();

        // ---- prefetch chunk c+1 while computing on chunk c ----
        if (c < 7) {
            const uint4* bp2 = bpack + (size_t)(c + 1) * 2 * 1280;
#pragma unroll
            for (int i = 0; i < 5; ++i) bpre[i] = bp2[tid + i * 256];
            if (AMODE == 0) {
                const float4* ap = (const float4*)(A + (size_t)(m0 + arow) * 256 + (c + 1) * 32 + kq);
                a4[0] = ap[0]; a4[1] = ap[1];
            }
        }

        // ---- mma over this chunk: 2 k16 steps x 3 split terms ----
#pragma unroll
        for (int ks = 0; ks < 2; ++ks) {
            uint32_t ah[2][4], al[2][4];
#pragma unroll
            for (int mt = 0; mt < 2; ++mt) {
                const uint32_t ra = sb + (uint32_t)(warp_m * 32 + mt * 16 + (lane & 15)) * 80
                                  + ks * 32 + ((lane >> 4) << 4);
                LDM_X4(ah[mt][0], ah[mt][1], ah[mt][2], ah[mt][3], ra);
                LDM_X4(al[mt][0], al[mt][1], al[mt][2], al[mt][3], ra + OFF_AL);
            }
            uint32_t bh[4][2], bl[4][2];
#pragma unroll
            for (int np = 0; np < 2; ++np) {
                const uint32_t rb = sb + OFF_BH
                                  + (uint32_t)(warp_n * 32 + np * 16 + (lane & 7) + ((lane >> 4) << 3)) * 80
                                  + ks * 32 + ((lane & 8) ? 16 : 0);
                LDM_X4(bh[2 * np][0], bh[2 * np][1], bh[2 * np + 1][0], bh[2 * np + 1][1], rb);
                LDM_X4(bl[2 * np][0], bl[2 * np][1], bl[2 * np + 1][0], bl[2 * np + 1][1], rb + 10240);
            }
#pragma unroll
            for (int mt = 0; mt < 2; ++mt)
#pragma unroll
                for (int nt = 0; nt < 4; ++nt) {
                    MMA16816(acc[mt][nt], ah[mt], bh[nt]);
                    MMA16816(acc[mt][nt], ah[mt], bl[nt]);
                    MMA16816(acc[mt][nt], al[mt], bh[nt]);
                }
        }
    }

    // ---- epilogue ----
    const int r_base = m0 + warp_m * 32 + (lane >> 2);
    const int c_base = n0 + warp_n * 32 + (lane & 3) * 2;
#pragma unroll
    for (int mt = 0; mt < 2; ++mt) {
#pragma unroll
        for (int half = 0; half < 2; ++half) {
            const int row = r_base + mt * 16 + half * 8;
            float *xp = nullptr, *vp = nullptr;
            if (EPI == 2) {
                const size_t g = ((size_t)row / 24) * 25 + (row % 24);
                xp = g_X + g * 256;
                vp = g_V + g * 256;
            }
#pragma unroll
            for (int nt = 0; nt < 4; ++nt) {
                const int col = c_base + nt * 8;
                float ox = acc[mt][nt][half * 2 + 0];
                float oy = acc[mt][nt][half * 2 + 1];
                if (bias) {
                    const float2 bv = *(const float2*)(bias + col);
                    ox += bv.x; oy += bv.y;
                }
                if (EPI == 1) { ox = fmaxf(ox, 0.f); oy = fmaxf(oy, 0.f); }
                if (EPI == 2) {
                    float2 xo = *(float2*)(xp + col);
                    xo.x += ox; xo.y += oy;
                    *(float2*)(xp + col) = xo;
                    float2 vo = *(float2*)(vp + col);
                    vo.x += ox; vo.y += oy;
                    *(float2*)(vp + col) = vo;
                } else {
                    *(float2*)(C + (size_t)row * 256 + col) = make_float2(ox, oy);
                }
            }
        }
    }
}

// ---------------- assemble X = qa - k, V = v, and d-rows ----------------
__global__ __launch_bounds__(256)
void assemble_kernel(const float* __restrict__ xyz_q,
                     const float* __restrict__ xyz,
                     const float* __restrict__ closest) {
    const int bq = blockIdx.x;
    const int b  = bq >> 12;
    const int t  = threadIdx.x;
    __shared__ float qa_s[DIM];
    __shared__ int   knn_s[KNN_K];
    __shared__ float q3[3];
    qa_s[t] = g_qa[b * DIM + t];
    if (t < KNN_K) knn_s[t] = g_knn[(size_t)bq * KNN_K + t];
    if (t < 3)     q3[t]    = xyz_q[(size_t)bq * 3 + t];
    __syncthreads();

    const size_t xb = (size_t)bq * NB * DIM;
    const float qv = qa_s[t];
#pragma unroll
    for (int j = 0; j < KNN_K; ++j) {
        const int i = knn_s[j];
        const size_t src = (size_t)(b * NPTS + i) * DIM + t;
        g_X[xb + j * DIM + t] = qv - g_kp[src];
        g_V[xb + j * DIM + t] = g_vp[src];
        if (t < 3)
            g_db[(size_t)(bq * 24 + j) * 4 + t] = q3[t] - xyz[(size_t)(b * NPTS + i) * 3 + t];
    }
#pragma unroll
    for (int g = 0; g < KG2; ++g) {
        const size_t src = (size_t)(bq * KG2 + g) * DIM + t;
        g_X[xb + (KNN_K + g) * DIM + t] = qv - g_gk[src];
        g_V[xb + (KNN_K + g) * DIM + t] = g_gv[src];
        if (t < 3)
            g_db[(size_t)(bq * 24 + KNN_K + g) * 4 + t] = q3[t] - closest[(size_t)(bq * KG2 + g) * 3 + t];
    }
    g_X[xb + 24 * DIM + t] = qv - g_kgl[b * DIM + t];
    g_V[xb + 24 * DIM + t] = g_vgl[b * DIM + t];
}

// ---------------- final: per-channel softmax over 25 neighbors, dot with V ------
__global__ __launch_bounds__(256)
void final_kernel(float* __restrict__ out) {
    const int bq = blockIdx.x;
    const int f  = threadIdx.x;
    const size_t base = (size_t)bq * NB * DIM + f;
    float a[NB];
#pragma unroll
    for (int j = 0; j < NB; ++j) a[j] = g_X[base + j * DIM];
    float m = a[0];
#pragma unroll
    for (int j = 1; j < NB; ++j) m = fmaxf(m, a[j]);
    float s = 0.f, o = 0.f;
#pragma unroll
    for (int j = 0; j < NB; ++j) {
        const float w = expf(a[j] - m);
        s += w;
        o = fmaf(w, g_V[base + j * DIM], o);
    }
    out[(size_t)bq * DIM + f] = o / s;
}

// ---------------- launch ----------------
extern "C" void kernel_launch(void* const* d_in, const int* in_sizes, int n_in,
                              void* d_out, int out_size) {
    const float* xyz_q  = (const float*)d_in[0];
    const float* lat    = (const float*)d_in[1];
    const float* xyz    = (const float*)d_in[2];
    const float* points = (const float*)d_in[3];
    const float* sgf    = (const float*)d_in[4];
    const float* closest= (const float*)d_in[5];
    const float* w_qs   = (const float*)d_in[6];
    const float* w_ks   = (const float*)d_in[7];
    const float* w_vs   = (const float*)d_in[8];
    const float* w_kc   = (const float*)d_in[9];
    const float* w_vc   = (const float*)d_in[10];
    const float* w_kg   = (const float*)d_in[11];
    const float* w_vg   = (const float*)d_in[12];
    const float* dw1    = (const float*)d_in[13];
    const float* db1    = (const float*)d_in[14];
    const float* dw2    = (const float*)d_in[15];
    const float* db2    = (const float*)d_in[16];
    const float* gw1    = (const float*)d_in[17];
    const float* gb1    = (const float*)d_in[18];
    const float* gw2    = (const float*)d_in[19];
    const float* gb2    = (const float*)d_in[20];

    float *kp, *vp, *gk, *gv, *X, *A1;
    cudaGetSymbolAddress((void**)&kp, g_kp);
    cudaGetSymbolAddress((void**)&vp, g_vp);
    cudaGetSymbolAddress((void**)&gk, g_gk);
    cudaGetSymbolAddress((void**)&gv, g_gv);
    cudaGetSymbolAddress((void**)&X,  g_X);
    cudaGetSymbolAddress((void**)&A1, g_A1);

    cudaFuncSetAttribute(gemm_mma_kernel<0, 0>, cudaFuncAttributeMaxDynamicSharedMemorySize, SMEM_DYN);
    cudaFuncSetAttribute(gemm_mma_kernel<0, 1>, cudaFuncAttributeMaxDynamicSharedMemorySize, SMEM_DYN);
    cudaFuncSetAttribute(gemm_mma_kernel<1, 2>, cudaFuncAttributeMaxDynamicSharedMemorySize, SMEM_DYN);

    // weight pack order: 0=w_ks 1=w_vs 2=w_kc 3=w_vc 4=dw2 5=gw1 6=gw2
    prepack_kernel<<<112, 256>>>(w_ks, w_vs, w_kc, w_vc, dw2, gw1, gw2);

    knn_kernel<<<dim3(NQ / 64, BATCH), 256>>>(xyz_q, xyz);

    gemm_mma_kernel<0, 0><<<dim3((BATCH * NPTS) / 64, 2), 256, SMEM_DYN>>>(points, 0, nullptr, kp, nullptr, nullptr);
    gemm_mma_kernel<0, 0><<<dim3((BATCH * NPTS) / 64, 2), 256, SMEM_DYN>>>(points, 1, nullptr, vp, nullptr, nullptr);
    gemm_mma_kernel<0, 0><<<dim3((BATCH * NQ * KG2) / 64, 2), 256, SMEM_DYN>>>(sgf, 2, nullptr, gk, nullptr, nullptr);
    gemm_mma_kernel<0, 0><<<dim3((BATCH * NQ * KG2) / 64, 2), 256, SMEM_DYN>>>(sgf, 3, nullptr, gv, nullptr, nullptr);

    proj_small_kernel<<<BATCH, 256>>>(lat, w_qs, w_kg, w_vg);

    assemble_kernel<<<BATCH * NQ, 256>>>(xyz_q, xyz, closest);

    // pos layer2 (layer1 fused into A producer); epilogue accumulates into X and V
    gemm_mma_kernel<1, 2><<<dim3((BATCH * NQ * 24) / 64, 2), 256, SMEM_DYN>>>(nullptr, 4, db2, nullptr, dw1, db1);

    // gamma MLP
    gemm_mma_kernel<0, 1><<<dim3((BATCH * NQ * NB) / 64, 2), 256, SMEM_DYN>>>(X,  5, gb1, A1, nullptr, nullptr);
    gemm_mma_kernel<0, 0><<<dim3((BATCH * NQ * NB) / 64, 2), 256, SMEM_DYN>>>(A1, 6, gb2, X,  nullptr, nullptr);

    final_kernel<<<BATCH * NQ, 256>>>((float*)d_out);
}

// round 11
// speedup vs baseline: 1.6297x; 1.0739x over previous
#include <cuda_runtime.h>
#include <cuda_bf16.h>
#include <cstdint>

// ---------------- problem constants ----------------
#define BATCH 2
#define NQ    4096
#define NPTS  8192
#define DIM   256
#define KNN_K 16
#define KG2   8
#define NB    25
#define XROWS 204800            // BATCH*NQ*NB
#define POSROWS 196608          // BATCH*NQ*24
#define FLT_BIG 3.402823466e+38f

// ---------------- scratch (device globals; no allocations) ----------------
__device__ float g_kp [BATCH * NPTS * DIM];
__device__ float g_vp [BATCH * NPTS * DIM];
__device__ float g_gk [BATCH * NQ * KG2 * DIM];
__device__ float g_gv [BATCH * NQ * KG2 * DIM];
__device__ float g_qa [BATCH * DIM];
__device__ float g_kgl[BATCH * DIM];
__device__ float g_vgl[BATCH * DIM];
__device__ int   g_knn[BATCH * NQ * KNN_K];
__device__ float g_db [BATCH * NQ * 24 * 4];
__device__ float g_V  [(size_t)XROWS * DIM];
__device__ float g_Xf [(size_t)XROWS * DIM];     // gamma2 output (logits)
// packed bf16 hi/lo A-operand planes: layout ((plane*8 + chunk)*Mtot + row)*80 + (col%32)*2
__device__ char  g_Xpack [(size_t)2 * 8 * XROWS * 80];
__device__ char  g_A1pack[(size_t)2 * 8 * XROWS * 80];
__device__ char  g_Ppack [(size_t)2 * 8 * (BATCH * NPTS) * 80];
__device__ char  g_Spack [(size_t)2 * 8 * (BATCH * NQ * KG2) * 80];
// prepacked weights: 7 weights x 8 k-chunks x 2 n-blocks, each region =
// [hi: 128 n-rows x 40 bf16][lo: same] = 20480 B
__device__ uint4 g_Bpack[7 * 8 * 2 * 1280];

// ---------------- PTX helpers (portable, no 'a'-gated features) ----------------
#define LDM_X4(r0, r1, r2, r3, addr) \
    asm volatile("ldmatrix.sync.aligned.m8n8.x4.shared.b16 {%0,%1,%2,%3}, [%4];" \
        : "=r"(r0), "=r"(r1), "=r"(r2), "=r"(r3) : "r"(addr))

#define MMA16816(d, a, b) \
    asm volatile("mma.sync.aligned.m16n8k16.row.col.f32.bf16.bf16.f32 " \
        "{%0,%1,%2,%3}, {%4,%5,%6,%7}, {%8,%9}, {%0,%1,%2,%3};" \
        : "+f"((d)[0]), "+f"((d)[1]), "+f"((d)[2]), "+f"((d)[3]) \
        : "r"((a)[0]), "r"((a)[1]), "r"((a)[2]), "r"((a)[3]), \
          "r"((b)[0]), "r"((b)[1]))

#define CP_ASYNC16(dst, src) \
    asm volatile("cp.async.cg.shared.global [%0], [%1], 16;" :: "r"(dst), "l"(src))
#define CP_COMMIT() asm volatile("cp.async.commit_group;" ::: "memory")
#define CP_WAIT1()  asm volatile("cp.async.wait_group 1;" ::: "memory")
#define CP_WAIT0()  asm volatile("cp.async.wait_group 0;" ::: "memory")

__device__ __forceinline__ uint32_t smem_u32(const void* p) {
    uint32_t a;
    asm("{ .reg .u64 t; cvta.to.shared.u64 t, %1; cvt.u32.u64 %0, t; }" : "=r"(a) : "l"(p));
    return a;
}

// two fp32 -> packed bf16 hi pair + lo (residual) pair
__device__ __forceinline__ void split2(float a, float b, uint32_t& h, uint32_t& l) {
    __nv_bfloat16 ha = __float2bfloat16(a), hb = __float2bfloat16(b);
    float ra = a - __bfloat162float(ha);
    float rb = b - __bfloat162float(hb);
    h = (uint32_t)__bfloat16_as_ushort(ha) | ((uint32_t)__bfloat16_as_ushort(hb) << 16);
    __nv_bfloat16 la = __float2bfloat16(ra), lb = __float2bfloat16(rb);
    l = (uint32_t)__bfloat16_as_ushort(la) | ((uint32_t)__bfloat16_as_ushort(lb) << 16);
}

// packed-plane byte offset
__device__ __forceinline__ size_t pk_off(int plane, int chunk, size_t Mtot, size_t row, int within) {
    return ((size_t)(plane * 8 + chunk) * Mtot + row) * 80 + (size_t)within * 2;
}

// SMEM stage layout (bytes): [A_hi 5120][A_lo 5120][B_hi 10240][B_lo 10240]
#define STG   30720
#define SA_LO 5120
#define SB_HI 10240
#define SMEM_DYN (3 * STG)

// ---------------- KNN: 64 queries x 4 point-chunks per block ----------------
__global__ __launch_bounds__(256)
void knn_kernel(const float* __restrict__ xyz_q, const float* __restrict__ xyz) {
    const int b      = blockIdx.y;
    const int tid    = threadIdx.x;
    const int qlocal = tid & 63;
    const int chunk  = tid >> 6;
    const int q      = blockIdx.x * 64 + qlocal;

    __shared__ float4 sp[1024];
    __shared__ float  sd[4][64][KNN_K];
    __shared__ int    si[4][64][KNN_K];

    const size_t qb = (size_t)(b * NQ + q) * 3;
    const float qx = xyz_q[qb + 0], qy = xyz_q[qb + 1], qz = xyz_q[qb + 2];
    const float qq = qx * qx + qy * qy + qz * qz;

    float dist[KNN_K];
    int   idx [KNN_K];
#pragma unroll
    for (int j = 0; j < KNN_K; ++j) { dist[j] = FLT_BIG; idx[j] = 0; }

    for (int tile = 0; tile < 8; ++tile) {
        const int t0 = tile * 1024;
        __syncthreads();
        for (int i = tid; i < 1024; i += 256) {
            const size_t pb = (size_t)(b * NPTS + t0 + i) * 3;
            float x = xyz[pb + 0], y = xyz[pb + 1], z = xyz[pb + 2];
            sp[i] = make_float4(x, y, z, x * x + y * y + z * z);
        }
        __syncthreads();
        if ((tile & 3) != chunk) continue;
#pragma unroll 4
        for (int i = 0; i < 1024; ++i) {
            const float4 P = sp[i];
            const float dot = qx * P.x + qy * P.y + qz * P.z;
            const float d2  = (qq + P.w) - 2.0f * dot;
            if (d2 < dist[KNN_K - 1]) {
                dist[KNN_K - 1] = d2; idx[KNN_K - 1] = t0 + i;
#pragma unroll
                for (int j = KNN_K - 1; j > 0; --j) {
                    if (dist[j] < dist[j - 1]) {
                        float td = dist[j]; dist[j] = dist[j - 1]; dist[j - 1] = td;
                        int   ti = idx[j];  idx[j]  = idx[j - 1];  idx[j - 1]  = ti;
                    }
                }
            }
        }
    }
#pragma unroll
    for (int j = 0; j < KNN_K; ++j) {
        sd[chunk][qlocal][j] = dist[j];
        si[chunk][qlocal][j] = idx[j];
    }
    __syncthreads();
    if (tid < 64) {
        const int qg = blockIdx.x * 64 + tid;
        int p0 = 0, p1 = 0, p2 = 0, p3 = 0;
#pragma unroll
        for (int j = 0; j < KNN_K; ++j) {
            const float v0 = (p0 < KNN_K) ? sd[0][tid][p0] : FLT_BIG;
            const float v1 = (p1 < KNN_K) ? sd[1][tid][p1] : FLT_BIG;
            const float v2 = (p2 < KNN_K) ? sd[2][tid][p2] : FLT_BIG;
            const float v3 = (p3 < KNN_K) ? sd[3][tid][p3] : FLT_BIG;
            int best;
            float m01 = fminf(v0, v1), m23 = fminf(v2, v3);
            if (fminf(m01, m23) == v0)      best = 0;
            else if (m01 <= m23)            best = 1;
            else if (m23 == v2)             best = 2;
            else                            best = 3;
            int pick;
            if      (best == 0) { pick = si[0][tid][p0]; ++p0; }
            else if (best == 1) { pick = si[1][tid][p1]; ++p1; }
            else if (best == 2) { pick = si[2][tid][p2]; ++p2; }
            else                { pick = si[3][tid][p3]; ++p3; }
            g_knn[(size_t)(b * NQ + qg) * KNN_K + j] = pick;
        }
    }
}

// ---------------- tiny projections ----------------
__global__ __launch_bounds__(256)
void proj_small_kernel(const float* __restrict__ lat,
                       const float* __restrict__ w_qs,
                       const float* __restrict__ w_kg,
                       const float* __restrict__ w_vg) {
    const int b = blockIdx.x, t = threadIdx.x;
    __shared__ float ls[DIM];
    ls[t] = lat[b * DIM + t];
    __syncthreads();
    float aq = 0.f, ak = 0.f, av = 0.f;
    for (int i = 0; i < DIM; ++i) {
        const float l = ls[i];
        aq = fmaf(l, w_qs[i * DIM + t], aq);
        ak = fmaf(l, w_kg[i * DIM + t], ak);
        av = fmaf(l, w_vg[i * DIM + t], av);
    }
    g_qa [b * DIM + t] = aq;
    g_kgl[b * DIM + t] = ak;
    g_vgl[b * DIM + t] = av;
}

// ---------------- weight prepack (unchanged layout) ----------------
__global__ __launch_bounds__(256)
void prepack_kernel(const float* __restrict__ w0, const float* __restrict__ w1,
                    const float* __restrict__ w2, const float* __restrict__ w3,
                    const float* __restrict__ w4, const float* __restrict__ w5,
                    const float* __restrict__ w6) {
    const float* Ws[7] = {w0, w1, w2, w3, w4, w5, w6};
    const int bid = blockIdx.x;
    const int w = bid >> 4, kc = (bid >> 1) & 7, nblk = bid & 1;
    const float* W = Ws[w];
    char* dst = (char*)g_Bpack + (size_t)bid * 20480;
#pragma unroll
    for (int i = 0; i < 16; ++i) {
        const int idx = threadIdx.x + i * 256;
        const int n_local = idx >> 5, k_local = idx & 31;
        const int n = nblk * 128 + n_local;
        const int k = kc * 32 + k_local;
        const float x = W[(size_t)k * 256 + n];
        __nv_bfloat16 h = __float2bfloat16(x);
        float lo = x - __bfloat162float(h);
        *(__nv_bfloat16*)(dst + n_local * 80 + k_local * 2)         = h;
        *(__nv_bfloat16*)(dst + 10240 + n_local * 80 + k_local * 2) = __float2bfloat16(lo);
    }
}

// ---------------- A prepack: fp32 [M,256] -> hi/lo plane format ----------------
__global__ __launch_bounds__(256)
void pack_a_kernel(const float* __restrict__ A, char* __restrict__ dst, int Mtot) {
    const size_t row = (size_t)blockIdx.x * 2 + (threadIdx.x >> 7);
    const int cp = threadIdx.x & 127;
    const int col = cp * 2;
    const float2 v = *(const float2*)(A + row * 256 + col);
    uint32_t h, l;
    split2(v.x, v.y, h, l);
    const int chunk = col >> 5, within = col & 31;
    *(uint32_t*)(dst + pk_off(0, chunk, (size_t)Mtot, row, within)) = h;
    *(uint32_t*)(dst + pk_off(1, chunk, (size_t)Mtot, row, within)) = l;
}

// ---------------- db + global-token row24 ----------------
__global__ __launch_bounds__(256)
void db_kernel(const float* __restrict__ xyz_q,
               const float* __restrict__ xyz,
               const float* __restrict__ closest) {
    const int bq = blockIdx.x;
    const int b  = bq >> 12;
    const int t  = threadIdx.x;
    __shared__ int   knn_s[KNN_K];
    __shared__ float q3[3];
    if (t < KNN_K) knn_s[t] = g_knn[(size_t)bq * KNN_K + t];
    if (t < 3)     q3[t]    = xyz_q[(size_t)bq * 3 + t];
    __syncthreads();

    if (t < 72) {
        const int j = t / 3, d = t % 3;
        float src;
        if (j < KNN_K) src = xyz[(size_t)(b * NPTS + knn_s[j]) * 3 + d];
        else           src = closest[((size_t)bq * KG2 + (j - KNN_K)) * 3 + d];
        g_db[(size_t)(bq * 24 + j) * 4 + d] = q3[d] - src;
    }
    // global token: X row24 packed = qa - kgl, V row24 = vgl
    const size_t grow = (size_t)bq * NB + 24;
    if (t < 128) {
        const int col = t * 2;
        const float2 qa2 = *(const float2*)(g_qa  + b * 256 + col);
        const float2 kg2 = *(const float2*)(g_kgl + b * 256 + col);
        uint32_t h, l;
        split2(qa2.x - kg2.x, qa2.y - kg2.y, h, l);
        const int chunk = col >> 5, within = col & 31;
        *(uint32_t*)(g_Xpack + pk_off(0, chunk, XROWS, grow, within)) = h;
        *(uint32_t*)(g_Xpack + pk_off(1, chunk, XROWS, grow, within)) = l;
    }
    g_V[grow * 256 + t] = g_vgl[b * 256 + t];
}

// ---------------- cp.async mma GEMM: C[M x 256] = A @ W (bf16x3) ----------------
// CTA tile M64 x N128 (blockIdx.y = n-half), 8 warps 2(m) x 4(n), K chunk 32, 3 stages.
// ASRC 0: A from packed planes (pure cp.async).  ASRC 1: A = relu(d @ W1 + b1) from g_db.
// EPI 0: C = acc (+bias) fp32.  EPI 1: relu + write packed A1.  EPI 2: pos gather -> X packed + V.
template<int ASRC, int EPI>
__global__ __launch_bounds__(256, 2)
void gemm_cp_kernel(const char* __restrict__ Apack, size_t Mtot, int widx,
                    const float* __restrict__ bias, float* __restrict__ C,
                    const float* __restrict__ W1, const float* __restrict__ b1) {
    extern __shared__ char smem_dyn[];
    const uint32_t sb0 = smem_u32(smem_dyn);
    const int tid = threadIdx.x, lane = tid & 31, wid = tid >> 5;
    const int warp_n = wid & 3, warp_m = wid >> 2;
    const size_t m0 = (size_t)blockIdx.x * 64;
    const int n0 = blockIdx.y * 128;

    const char* bbase = (const char*)g_Bpack + ((size_t)(widx * 8) * 2 + blockIdx.y) * 20480;

    float acc[2][4][4];
#pragma unroll
    for (int mt = 0; mt < 2; ++mt)
#pragma unroll
        for (int nt = 0; nt < 4; ++nt)
#pragma unroll
            for (int j = 0; j < 4; ++j) acc[mt][nt][j] = 0.f;

    // DB producer state
    const int arow = tid >> 2, kq = (tid & 3) * 8;
    float4 dd;
    if (ASRC == 1) dd = *(const float4*)(g_db + (m0 + arow) * 4);

    // ---- issue helpers ----
#define ISSUE_CHUNK(c_, buf_) do {                                              \
        const char* bsrc_ = bbase + (size_t)(c_) * 40960;                       \
        const uint32_t bdst_ = sb0 + (buf_) * STG + SB_HI;                      \
        _Pragma("unroll")                                                       \
        for (int i_ = tid; i_ < 1280; i_ += 256)                                \
            CP_ASYNC16(bdst_ + i_ * 16, bsrc_ + (size_t)i_ * 16);               \
        if (ASRC == 0) {                                                        \
            _Pragma("unroll")                                                   \
            for (int i_ = tid; i_ < 640; i_ += 256) {                           \
                const int p_ = i_ / 320, l_ = i_ - p_ * 320;                    \
                const char* asrc_ = Apack +                                     \
                    ((size_t)(p_ * 8 + (c_)) * Mtot + m0) * 80 + (size_t)l_ * 16; \
                CP_ASYNC16(sb0 + (buf_) * STG + p_ * SA_LO + l_ * 16, asrc_);   \
            }                                                                   \
        }                                                                       \
        CP_COMMIT();                                                            \
    } while (0)

    ISSUE_CHUNK(0, 0);
    ISSUE_CHUNK(1, 1);

    for (int c = 0; c < 8; ++c) {
        const int buf = c % 3;
        if (c < 6) CP_WAIT1(); else CP_WAIT0();
        __syncthreads();
        if (c + 2 < 8) ISSUE_CHUNK(c + 2, (c + 2) % 3);

        if (ASRC == 1) {
            float v[8];
#pragma unroll
            for (int i = 0; i < 8; ++i) {
                const int k = c * 32 + kq + i;
                float h = fmaf(dd.x, W1[k], fmaf(dd.y, W1[256 + k], fmaf(dd.z, W1[512 + k], b1[k])));
                v[i] = fmaxf(h, 0.f);
            }
            uint4 h0, l0;
            split2(v[0], v[1], h0.x, l0.x); split2(v[2], v[3], h0.y, l0.y);
            split2(v[4], v[5], h0.z, l0.z); split2(v[6], v[7], h0.w, l0.w);
            char* stc = smem_dyn + buf * STG;
            *(uint4*)(stc + arow * 80 + kq * 2)         = h0;
            *(uint4*)(stc + SA_LO + arow * 80 + kq * 2) = l0;
            __syncthreads();
        }

        const uint32_t sb = sb0 + buf * STG;
#pragma unroll
        for (int ks = 0; ks < 2; ++ks) {
            uint32_t ah[2][4], al[2][4];
#pragma unroll
            for (int mt = 0; mt < 2; ++mt) {
                const uint32_t ra = sb + (uint32_t)(warp_m * 32 + mt * 16 + (lane & 15)) * 80
                                  + ks * 32 + ((lane >> 4) << 4);
                LDM_X4(ah[mt][0], ah[mt][1], ah[mt][2], ah[mt][3], ra);
                LDM_X4(al[mt][0], al[mt][1], al[mt][2], al[mt][3], ra + SA_LO);
            }
            uint32_t bh[4][2], bl[4][2];
#pragma unroll
            for (int np = 0; np < 2; ++np) {
                const uint32_t rb = sb + SB_HI
                                  + (uint32_t)(warp_n * 32 + np * 16 + (lane & 7) + ((lane >> 4) << 3)) * 80
                                  + ks * 32 + ((lane & 8) ? 16 : 0);
                LDM_X4(bh[2 * np][0], bh[2 * np][1], bh[2 * np + 1][0], bh[2 * np + 1][1], rb);
                LDM_X4(bl[2 * np][0], bl[2 * np][1], bl[2 * np + 1][0], bl[2 * np + 1][1], rb + 10240);
            }
#pragma unroll
            for (int mt = 0; mt < 2; ++mt)
#pragma unroll
                for (int nt = 0; nt < 4; ++nt) {
                    MMA16816(acc[mt][nt], ah[mt], bh[nt]);
                    MMA16816(acc[mt][nt], ah[mt], bl[nt]);
                    MMA16816(acc[mt][nt], al[mt], bh[nt]);
                }
        }
    }
#undef ISSUE_CHUNK

    // ---- epilogue ----
    const size_t r_base = m0 + warp_m * 32 + (lane >> 2);
    const int c_base = n0 + warp_n * 32 + (lane & 3) * 2;
#pragma unroll
    for (int mt = 0; mt < 2; ++mt) {
#pragma unroll
        for (int half = 0; half < 2; ++half) {
            const size_t row = r_base + mt * 16 + half * 8;
            const float* ksrc = nullptr;
            const float* vsrc = nullptr;
            const float* qrow = nullptr;
            size_t grow = row;
            if (EPI == 2) {
                const size_t bq = row / 24;
                const int j = (int)(row % 24);
                const int b = (int)(bq >> 12);
                grow = bq * NB + j;
                if (j < KNN_K) {
                    const int pi = g_knn[bq * KNN_K + j];
                    const size_t o = ((size_t)(b * NPTS) + pi) * 256;
                    ksrc = g_kp + o; vsrc = g_vp + o;
                } else {
                    const size_t o = (bq * KG2 + (j - KNN_K)) * 256;
                    ksrc = g_gk + o; vsrc = g_gv + o;
                }
                qrow = g_qa + b * 256;
            }
#pragma unroll
            for (int nt = 0; nt < 4; ++nt) {
                const int col = c_base + nt * 8;
                float ox = acc[mt][nt][half * 2 + 0];
                float oy = acc[mt][nt][half * 2 + 1];
                if (bias) {
                    const float2 bv = *(const float2*)(bias + col);
                    ox += bv.x; oy += bv.y;
                }
                if (EPI == 0) {
                    *(float2*)(C + row * 256 + col) = make_float2(ox, oy);
                } else if (EPI == 1) {
                    ox = fmaxf(ox, 0.f); oy = fmaxf(oy, 0.f);
                    uint32_t h, l;
                    split2(ox, oy, h, l);
                    const int chunk = col >> 5, within = col & 31;
                    *(uint32_t*)(g_A1pack + pk_off(0, chunk, XROWS, row, within)) = h;
                    *(uint32_t*)(g_A1pack + pk_off(1, chunk, XROWS, row, within)) = l;
                } else {
                    const float2 kk = *(const float2*)(ksrc + col);
                    const float2 vv = *(const float2*)(vsrc + col);
                    const float2 qq = *(const float2*)(qrow + col);
                    const float xa = qq.x - kk.x + ox;
                    const float xb = qq.y - kk.y + oy;
                    uint32_t h, l;
                    split2(xa, xb, h, l);
                    const int chunk = col >> 5, within = col & 31;
                    *(uint32_t*)(g_Xpack + pk_off(0, chunk, XROWS, grow, within)) = h;
                    *(uint32_t*)(g_Xpack + pk_off(1, chunk, XROWS, grow, within)) = l;
                    *(float2*)(g_V + grow * 256 + col) = make_float2(vv.x + ox, vv.y + oy);
                }
            }
        }
    }
}

// ---------------- final: per-channel softmax over 25 neighbors, dot with V ------
__global__ __launch_bounds__(256)
void final_kernel(float* __restrict__ out) {
    const int bq = blockIdx.x;
    const int f  = threadIdx.x;
    const size_t base = (size_t)bq * NB * DIM + f;
    float a[NB];
#pragma unroll
    for (int j = 0; j < NB; ++j) a[j] = g_Xf[base + j * DIM];
    float m = a[0];
#pragma unroll
    for (int j = 1; j < NB; ++j) m = fmaxf(m, a[j]);
    float s = 0.f, o = 0.f;
#pragma unroll
    for (int j = 0; j < NB; ++j) {
        const float w = expf(a[j] - m);
        s += w;
        o = fmaf(w, g_V[base + j * DIM], o);
    }
    out[(size_t)bq * DIM + f] = o / s;
}

// ---------------- launch ----------------
extern "C" void kernel_launch(void* const* d_in, const int* in_sizes, int n_in,
                              void* d_out, int out_size) {
    const float* xyz_q  = (const float*)d_in[0];
    const float* lat    = (const float*)d_in[1];
    const float* xyz    = (const float*)d_in[2];
    const float* points = (const float*)d_in[3];
    const float* sgf    = (const float*)d_in[4];
    const float* closest= (const float*)d_in[5];
    const float* w_qs   = (const float*)d_in[6];
    const float* w_ks   = (const float*)d_in[7];
    const float* w_vs   = (const float*)d_in[8];
    const float* w_kc   = (const float*)d_in[9];
    const float* w_vc   = (const float*)d_in[10];
    const float* w_kg   = (const float*)d_in[11];
    const float* w_vg   = (const float*)d_in[12];
    const float* dw1    = (const float*)d_in[13];
    const float* db1    = (const float*)d_in[14];
    const float* dw2    = (const float*)d_in[15];
    const float* db2    = (const float*)d_in[16];
    const float* gw1    = (const float*)d_in[17];
    const float* gb1    = (const float*)d_in[18];
    const float* gw2    = (const float*)d_in[19];
    const float* gb2    = (const float*)d_in[20];

    float *kp, *vp, *gk, *gv, *Xf;
    char *Ppk, *Spk, *Xpk, *A1pk;
    cudaGetSymbolAddress((void**)&kp,   g_kp);
    cudaGetSymbolAddress((void**)&vp,   g_vp);
    cudaGetSymbolAddress((void**)&gk,   g_gk);
    cudaGetSymbolAddress((void**)&gv,   g_gv);
    cudaGetSymbolAddress((void**)&Xf,   g_Xf);
    cudaGetSymbolAddress((void**)&Ppk,  g_Ppack);
    cudaGetSymbolAddress((void**)&Spk,  g_Spack);
    cudaGetSymbolAddress((void**)&Xpk,  g_Xpack);
    cudaGetSymbolAddress((void**)&A1pk, g_A1pack);

    cudaFuncSetAttribute(gemm_cp_kernel<0, 0>, cudaFuncAttributeMaxDynamicSharedMemorySize, SMEM_DYN);
    cudaFuncSetAttribute(gemm_cp_kernel<0, 1>, cudaFuncAttributeMaxDynamicSharedMemorySize, SMEM_DYN);
    cudaFuncSetAttribute(gemm_cp_kernel<1, 2>, cudaFuncAttributeMaxDynamicSharedMemorySize, SMEM_DYN);

    // weight pack order: 0=w_ks 1=w_vs 2=w_kc 3=w_vc 4=dw2 5=gw1 6=gw2
    prepack_kernel<<<112, 256>>>(w_ks, w_vs, w_kc, w_vc, dw2, gw1, gw2);
    pack_a_kernel<<<(BATCH * NPTS) / 2, 256>>>(points, Ppk, BATCH * NPTS);
    pack_a_kernel<<<(BATCH * NQ * KG2) / 2, 256>>>(sgf, Spk, BATCH * NQ * KG2);

    knn_kernel<<<dim3(NQ / 64, BATCH), 256>>>(xyz_q, xyz);
    proj_small_kernel<<<BATCH, 256>>>(lat, w_qs, w_kg, w_vg);

    gemm_cp_kernel<0, 0><<<dim3((BATCH * NPTS) / 64, 2), 256, SMEM_DYN>>>(Ppk, BATCH * NPTS, 0, nullptr, kp, nullptr, nullptr);
    gemm_cp_kernel<0, 0><<<dim3((BATCH * NPTS) / 64, 2), 256, SMEM_DYN>>>(Ppk, BATCH * NPTS, 1, nullptr, vp, nullptr, nullptr);
    gemm_cp_kernel<0, 0><<<dim3((BATCH * NQ * KG2) / 64, 2), 256, SMEM_DYN>>>(Spk, BATCH * NQ * KG2, 2, nullptr, gk, nullptr, nullptr);
    gemm_cp_kernel<0, 0><<<dim3((BATCH * NQ * KG2) / 64, 2), 256, SMEM_DYN>>>(Spk, BATCH * NQ * KG2, 3, nullptr, gv, nullptr, nullptr);

    db_kernel<<<BATCH * NQ, 256>>>(xyz_q, xyz, closest);

    // pos GEMM: layer1 fused in producer; epilogue gathers k/v and writes X-pack + V
    gemm_cp_kernel<1, 2><<<dim3(POSROWS / 64, 2), 256, SMEM_DYN>>>(nullptr, POSROWS, 4, db2, nullptr, dw1, db1);

    // gamma MLP
    gemm_cp_kernel<0, 1><<<dim3(XROWS / 64, 2), 256, SMEM_DYN>>>(Xpk, XROWS, 5, gb1, nullptr, nullptr, nullptr);
    gemm_cp_kernel<0, 0><<<dim3(XROWS / 64, 2), 256, SMEM_DYN>>>(A1pk, XROWS, 6, gb2, Xf, nullptr, nullptr);

    final_kernel<<<BATCH * NQ, 256>>>((float*)d_out);
}

// round 14
// speedup vs baseline: 2.2751x; 1.3961x over previous
#include <cuda_runtime.h>
#include <cuda_bf16.h>
#include <cstdint>

// ---------------- problem constants ----------------
#define BATCH 2
#define NQ    4096
#define NPTS  8192
#define DIM   256
#define KNN_K 16
#define KG2   8
#define NB    25
#define XROWS 204800            // BATCH*NQ*NB
#define POSROWS 196608          // BATCH*NQ*24
#define FLT_BIG 3.402823466e+38f

// ---------------- scratch (device globals; no allocations) ----------------
__device__ float g_kp [BATCH * NPTS * DIM];
__device__ float g_vp [BATCH * NPTS * DIM];
__device__ float g_gk [BATCH * NQ * KG2 * DIM];
__device__ float g_gv [BATCH * NQ * KG2 * DIM];
__device__ float g_qa [BATCH * DIM];
__device__ float g_kgl[BATCH * DIM];
__device__ float g_vgl[BATCH * DIM];
__device__ int   g_knn[BATCH * NQ * KNN_K];
__device__ float g_db [BATCH * NQ * 24 * 4];
__device__ float g_V  [(size_t)XROWS * DIM];
__device__ float g_Xf [(size_t)XROWS * DIM];     // gamma2 output (logits)
// packed bf16 hi/lo A-operand planes: layout ((plane*8 + chunk)*Mtot + row)*80 + (col%32)*2
__device__ char  g_Xpack [(size_t)2 * 8 * XROWS * 80];
__device__ char  g_A1pack[(size_t)2 * 8 * XROWS * 80];
__device__ char  g_Ppack [(size_t)2 * 8 * (BATCH * NPTS) * 80];
__device__ char  g_Spack [(size_t)2 * 8 * (BATCH * NQ * KG2) * 80];
// prepacked weights: 7 weights x 8 k-chunks x 2 n-blocks, each region =
// [hi: 128 n-rows x 40 bf16][lo: same] = 20480 B
__device__ uint4 g_Bpack[7 * 8 * 2 * 1280];

// ---------------- PTX helpers (portable, no 'a'-gated features) ----------------
#define LDM_X4(r0, r1, r2, r3, addr) \
    asm volatile("ldmatrix.sync.aligned.m8n8.x4.shared.b16 {%0,%1,%2,%3}, [%4];" \
        : "=r"(r0), "=r"(r1), "=r"(r2), "=r"(r3) : "r"(addr))

#define MMA16816(d, a, b) \
    asm volatile("mma.sync.aligned.m16n8k16.row.col.f32.bf16.bf16.f32 " \
        "{%0,%1,%2,%3}, {%4,%5,%6,%7}, {%8,%9}, {%0,%1,%2,%3};" \
        : "+f"((d)[0]), "+f"((d)[1]), "+f"((d)[2]), "+f"((d)[3]) \
        : "r"((a)[0]), "r"((a)[1]), "r"((a)[2]), "r"((a)[3]), \
          "r"((b)[0]), "r"((b)[1]))

#define CP_ASYNC16(dst, src) \
    asm volatile("cp.async.cg.shared.global [%0], [%1], 16;" :: "r"(dst), "l"(src))
#define CP_COMMIT() asm volatile("cp.async.commit_group;" ::: "memory")
#define CP_WAIT1()  asm volatile("cp.async.wait_group 1;" ::: "memory")
#define CP_WAIT0()  asm volatile("cp.async.wait_group 0;" ::: "memory")

__device__ __forceinline__ uint32_t smem_u32(const void* p) {
    uint32_t a;
    asm("{ .reg .u64 t; cvta.to.shared.u64 t, %1; cvt.u32.u64 %0, t; }" : "=r"(a) : "l"(p));
    return a;
}

// two fp32 -> packed bf16 hi pair + lo (residual) pair
__device__ __forceinline__ void split2(float a, float b, uint32_t& h, uint32_t& l) {
    __nv_bfloat16 ha = __float2bfloat16(a), hb = __float2bfloat16(b);
    float ra = a - __bfloat162float(ha);
    float rb = b - __bfloat162float(hb);
    h = (uint32_t)__bfloat16_as_ushort(ha) | ((uint32_t)__bfloat16_as_ushort(hb) << 16);
    __nv_bfloat16 la = __float2bfloat16(ra), lb = __float2bfloat16(rb);
    l = (uint32_t)__bfloat16_as_ushort(la) | ((uint32_t)__bfloat16_as_ushort(lb) << 16);
}

// packed-plane byte offset
__device__ __forceinline__ size_t pk_off(int plane, int chunk, size_t Mtot, size_t row, int within) {
    return ((size_t)(plane * 8 + chunk) * Mtot + row) * 80 + (size_t)within * 2;
}

// SMEM stage layout (bytes): [A_hi 5120][A_lo 5120][B_hi 10240][B_lo 10240]
#define STG   30720
#define SA_LO 5120
#define SB_HI 10240
#define SMEM_DYN (3 * STG)

// ---------------- KNN: 16 queries x 16 chunks per block, parallel tree merge ----
// Tie-break is lexicographic on (distance, index) so the merged result is
// EXACTLY what a single ascending-index scan with strict < would produce
// (matches jax.lax.top_k stable selection).
__global__ __launch_bounds__(256)
void knn_kernel(const float* __restrict__ xyz_q, const float* __restrict__ xyz) {
    const int b      = blockIdx.y;
    const int tid    = threadIdx.x;
    const int ql     = tid & 15;       // query within block
    const int chunk  = tid >> 4;       // 0..15
    const int q      = blockIdx.x * 16 + ql;

    __shared__ float4 sp[1024];
    __shared__ float  sd[16][16][KNN_K];   // [chunk][q][k]
    __shared__ int    si[16][16][KNN_K];

    const size_t qb = (size_t)(b * NQ + q) * 3;
    const float qx = xyz_q[qb + 0], qy = xyz_q[qb + 1], qz = xyz_q[qb + 2];
    const float qq = qx * qx + qy * qy + qz * qz;

    float dist[KNN_K];
    int   idx [KNN_K];
#pragma unroll
    for (int j = 0; j < KNN_K; ++j) { dist[j] = FLT_BIG; idx[j] = 0x7fffffff; }

    for (int tile = 0; tile < 8; ++tile) {
        const int t0 = tile * 1024;
        __syncthreads();
        for (int i = tid; i < 1024; i += 256) {
            const size_t pb = (size_t)(b * NPTS + t0 + i) * 3;
            float x = xyz[pb + 0], y = xyz[pb + 1], z = xyz[pb + 2];
            sp[i] = make_float4(x, y, z, x * x + y * y + z * z);
        }
        __syncthreads();
        const int base = chunk * 64;
#pragma unroll 4
        for (int i = 0; i < 64; ++i) {
            const float4 P = sp[base + i];
            const float dot = qx * P.x + qy * P.y + qz * P.z;
            const float d2  = (qq + P.w) - 2.0f * dot;
            if (d2 < dist[KNN_K - 1]) {
                dist[KNN_K - 1] = d2; idx[KNN_K - 1] = t0 + base + i;
#pragma unroll
                for (int j = KNN_K - 1; j > 0; --j) {
                    if (dist[j] < dist[j - 1]) {
                        float td = dist[j]; dist[j] = dist[j - 1]; dist[j - 1] = td;
                        int   ti = idx[j];  idx[j]  = idx[j - 1];  idx[j - 1]  = ti;
                    }
                }
            }
        }
    }
#pragma unroll
    for (int j = 0; j < KNN_K; ++j) {
        sd[chunk][ql][j] = dist[j];
        si[chunk][ql][j] = idx[j];
    }
    __syncthreads();

    // parallel pairwise tree merge: 16 -> 8 -> 4 -> 2 -> 1 sorted lists
#pragma unroll
    for (int stride = 1; stride < 16; stride <<= 1) {
        const int nm = 16 / (2 * stride);
        float od[KNN_K]; int oi[KNN_K];
        const int c0 = chunk * 2 * stride, c1 = c0 + stride;
        if (chunk < nm) {
            int i = 0, j = 0;
#pragma unroll
            for (int k = 0; k < KNN_K; ++k) {
                const float d0 = (i < KNN_K) ? sd[c0][ql][i] : FLT_BIG;
                const float d1 = (j < KNN_K) ? sd[c1][ql][j] : FLT_BIG;
                const int   x0 = (i < KNN_K) ? si[c0][ql][i] : 0x7fffffff;
                const int   x1 = (j < KNN_K) ? si[c1][ql][j] : 0x7fffffff;
                const bool take0 = (d0 < d1) || (d0 == d1 && x0 < x1);
                if (take0) { od[k] = d0; oi[k] = x0; ++i; }
                else       { od[k] = d1; oi[k] = x1; ++j; }
            }
        }
        __syncthreads();
        if (chunk < nm) {
            if (nm == 1) {
#pragma unroll
                for (int k = 0; k < KNN_K; ++k)
                    g_knn[(size_t)(b * NQ + q) * KNN_K + k] = oi[k];
            } else {
#pragma unroll
                for (int k = 0; k < KNN_K; ++k) {
                    sd[c0][ql][k] = od[k];
                    si[c0][ql][k] = oi[k];
                }
            }
        }
        __syncthreads();
    }
}

// ---------------- tiny projections ----------------
__global__ __launch_bounds__(256)
void proj_small_kernel(const float* __restrict__ lat,
                       const float* __restrict__ w_qs,
                       const float* __restrict__ w_kg,
                       const float* __restrict__ w_vg) {
    const int b = blockIdx.x, t = threadIdx.x;
    __shared__ float ls[DIM];
    ls[t] = lat[b * DIM + t];
    __syncthreads();
    float aq = 0.f, ak = 0.f, av = 0.f;
    for (int i = 0; i < DIM; ++i) {
        const float l = ls[i];
        aq = fmaf(l, w_qs[i * DIM + t], aq);
        ak = fmaf(l, w_kg[i * DIM + t], ak);
        av = fmaf(l, w_vg[i * DIM + t], av);
    }
    g_qa [b * DIM + t] = aq;
    g_kgl[b * DIM + t] = ak;
    g_vgl[b * DIM + t] = av;
}

// ---------------- weight prepack (unchanged layout) ----------------
__global__ __launch_bounds__(256)
void prepack_kernel(const float* __restrict__ w0, const float* __restrict__ w1,
                    const float* __restrict__ w2, const float* __restrict__ w3,
                    const float* __restrict__ w4, const float* __restrict__ w5,
                    const float* __restrict__ w6) {
    const float* Ws[7] = {w0, w1, w2, w3, w4, w5, w6};
    const int bid = blockIdx.x;
    const int w = bid >> 4, kc = (bid >> 1) & 7, nblk = bid & 1;
    const float* W = Ws[w];
    char* dst = (char*)g_Bpack + (size_t)bid * 20480;
#pragma unroll
    for (int i = 0; i < 16; ++i) {
        const int idx = threadIdx.x + i * 256;
        const int n_local = idx >> 5, k_local = idx & 31;
        const int n = nblk * 128 + n_local;
        const int k = kc * 32 + k_local;
        const float x = W[(size_t)k * 256 + n];
        __nv_bfloat16 h = __float2bfloat16(x);
        float lo = x - __bfloat162float(h);
        *(__nv_bfloat16*)(dst + n_local * 80 + k_local * 2)         = h;
        *(__nv_bfloat16*)(dst + 10240 + n_local * 80 + k_local * 2) = __float2bfloat16(lo);
    }
}

// ---------------- A prepack: fp32 [M,256] -> hi/lo plane format ----------------
__global__ __launch_bounds__(256)
void pack_a_kernel(const float* __restrict__ A, char* __restrict__ dst, int Mtot) {
    const size_t row = (size_t)blockIdx.x * 2 + (threadIdx.x >> 7);
    const int cp = threadIdx.x & 127;
    const int col = cp * 2;
    const float2 v = *(const float2*)(A + row * 256 + col);
    uint32_t h, l;
    split2(v.x, v.y, h, l);
    const int chunk = col >> 5, within = col & 31;
    *(uint32_t*)(dst + pk_off(0, chunk, (size_t)Mtot, row, within)) = h;
    *(uint32_t*)(dst + pk_off(1, chunk, (size_t)Mtot, row, within)) = l;
}

// ---------------- db + global-token row24 ----------------
__global__ __launch_bounds__(256)
void db_kernel(const float* __restrict__ xyz_q,
               const float* __restrict__ xyz,
               const float* __restrict__ closest) {
    const int bq = blockIdx.x;
    const int b  = bq >> 12;
    const int t  = threadIdx.x;
    __shared__ int   knn_s[KNN_K];
    __shared__ float q3[3];
    if (t < KNN_K) knn_s[t] = g_knn[(size_t)bq * KNN_K + t];
    if (t < 3)     q3[t]    = xyz_q[(size_t)bq * 3 + t];
    __syncthreads();

    if (t < 72) {
        const int j = t / 3, d = t % 3;
        float src;
        if (j < KNN_K) src = xyz[(size_t)(b * NPTS + knn_s[j]) * 3 + d];
        else           src = closest[((size_t)bq * KG2 + (j - KNN_K)) * 3 + d];
        g_db[(size_t)(bq * 24 + j) * 4 + d] = q3[d] - src;
    }
    // global token: X row24 packed = qa - kgl, V row24 = vgl
    const size_t grow = (size_t)bq * NB + 24;
    if (t < 128) {
        const int col = t * 2;
        const float2 qa2 = *(const float2*)(g_qa  + b * 256 + col);
        const float2 kg2 = *(const float2*)(g_kgl + b * 256 + col);
        uint32_t h, l;
        split2(qa2.x - kg2.x, qa2.y - kg2.y, h, l);
        const int chunk = col >> 5, within = col & 31;
        *(uint32_t*)(g_Xpack + pk_off(0, chunk, XROWS, grow, within)) = h;
        *(uint32_t*)(g_Xpack + pk_off(1, chunk, XROWS, grow, within)) = l;
    }
    g_V[grow * 256 + t] = g_vgl[b * 256 + t];
}

// ---------------- cp.async mma GEMM: C[M x 256] = A @ W (bf16x3) ----------------
// CTA tile M64 x N128 (blockIdx.y = n-half), 8 warps 2(m) x 4(n), K chunk 32, 3 stages.
// ASRC 0: A from packed planes (pure cp.async).  ASRC 1: A = relu(d @ W1 + b1) from g_db.
// EPI 0: C = acc (+bias) fp32.  EPI 1: relu + write packed A1.  EPI 2: pos gather -> X packed + V.
template<int ASRC, int EPI>
__global__ __launch_bounds__(256, 2)
void gemm_cp_kernel(const char* __restrict__ Apack, size_t Mtot, int widx,
                    const float* __restrict__ bias, float* __restrict__ C,
                    const float* __restrict__ W1, const float* __restrict__ b1) {
    extern __shared__ char smem_dyn[];
    const uint32_t sb0 = smem_u32(smem_dyn);
    const int tid = threadIdx.x, lane = tid & 31, wid = tid >> 5;
    const int warp_n = wid & 3, warp_m = wid >> 2;
    const size_t m0 = (size_t)blockIdx.x * 64;
    const int n0 = blockIdx.y * 128;

    const char* bbase = (const char*)g_Bpack + ((size_t)(widx * 8) * 2 + blockIdx.y) * 20480;

    float acc[2][4][4];
#pragma unroll
    for (int mt = 0; mt < 2; ++mt)
#pragma unroll
        for (int nt = 0; nt < 4; ++nt)
#pragma unroll
            for (int j = 0; j < 4; ++j) acc[mt][nt][j] = 0.f;

    // DB producer state
    const int arow = tid >> 2, kq = (tid & 3) * 8;
    float4 dd;
    if (ASRC == 1) dd = *(const float4*)(g_db + (m0 + arow) * 4);

    // ---- issue helpers ----
#define ISSUE_CHUNK(c_, buf_) do {                                              \
        const char* bsrc_ = bbase + (size_t)(c_) * 40960;                       \
        const uint32_t bdst_ = sb0 + (buf_) * STG + SB_HI;                      \
        _Pragma("unroll")                                                       \
        for (int i_ = tid; i_ < 1280; i_ += 256)                                \
            CP_ASYNC16(bdst_ + i_ * 16, bsrc_ + (size_t)i_ * 16);               \
        if (ASRC == 0) {                                                        \
            _Pragma("unroll")                                                   \
            for (int i_ = tid; i_ < 640; i_ += 256) {                           \
                const int p_ = i_ / 320, l_ = i_ - p_ * 320;                    \
                const char* asrc_ = Apack +                                     \
                    ((size_t)(p_ * 8 + (c_)) * Mtot + m0) * 80 + (size_t)l_ * 16; \
                CP_ASYNC16(sb0 + (buf_) * STG + p_ * SA_LO + l_ * 16, asrc_);   \
            }                                                                   \
        }                                                                       \
        CP_COMMIT();                                                            \
    } while (0)

    ISSUE_CHUNK(0, 0);
    ISSUE_CHUNK(1, 1);

    for (int c = 0; c < 8; ++c) {
        const int buf = c % 3;
        if (c < 6) CP_WAIT1(); else CP_WAIT0();
        __syncthreads();
        if (c + 2 < 8) ISSUE_CHUNK(c + 2, (c + 2) % 3);

        if (ASRC == 1) {
            float v[8];
#pragma unroll
            for (int i = 0; i < 8; ++i) {
                const int k = c * 32 + kq + i;
                float h = fmaf(dd.x, W1[k], fmaf(dd.y, W1[256 + k], fmaf(dd.z, W1[512 + k], b1[k])));
                v[i] = fmaxf(h, 0.f);
            }
            uint4 h0, l0;
            split2(v[0], v[1], h0.x, l0.x); split2(v[2], v[3], h0.y, l0.y);
            split2(v[4], v[5], h0.z, l0.z); split2(v[6], v[7], h0.w, l0.w);
            char* stc = smem_dyn + buf * STG;
            *(uint4*)(stc + arow * 80 + kq * 2)         = h0;
            *(uint4*)(stc + SA_LO + arow * 80 + kq * 2) = l0;
            __syncthreads();
        }

        const uint32_t sb = sb0 + buf * STG;
#pragma unroll
        for (int ks = 0; ks < 2; ++ks) {
            uint32_t ah[2][4], al[2][4];
#pragma unroll
            for (int mt = 0; mt < 2; ++mt) {
                const uint32_t ra = sb + (uint32_t)(warp_m * 32 + mt * 16 + (lane & 15)) * 80
                                  + ks * 32 + ((lane >> 4) << 4);
                LDM_X4(ah[mt][0], ah[mt][1], ah[mt][2], ah[mt][3], ra);
                LDM_X4(al[mt][0], al[mt][1], al[mt][2], al[mt][3], ra + SA_LO);
            }
            uint32_t bh[4][2], bl[4][2];
#pragma unroll
            for (int np = 0; np < 2; ++np) {
                const uint32_t rb = sb + SB_HI
                                  + (uint32_t)(warp_n * 32 + np * 16 + (lane & 7) + ((lane >> 4) << 3)) * 80
                                  + ks * 32 + ((lane & 8) ? 16 : 0);
                LDM_X4(bh[2 * np][0], bh[2 * np][1], bh[2 * np + 1][0], bh[2 * np + 1][1], rb);
                LDM_X4(bl[2 * np][0], bl[2 * np][1], bl[2 * np + 1][0], bl[2 * np + 1][1], rb + 10240);
            }
#pragma unroll
            for (int mt = 0; mt < 2; ++mt)
#pragma unroll
                for (int nt = 0; nt < 4; ++nt) {
                    MMA16816(acc[mt][nt], ah[mt], bh[nt]);
                    MMA16816(acc[mt][nt], ah[mt], bl[nt]);
                    MMA16816(acc[mt][nt], al[mt], bh[nt]);
                }
        }
    }
#undef ISSUE_CHUNK

    // ---- epilogue ----
    const size_t r_base = m0 + warp_m * 32 + (lane >> 2);
    const int c_base = n0 + warp_n * 32 + (lane & 3) * 2;
#pragma unroll
    for (int mt = 0; mt < 2; ++mt) {
#pragma unroll
        for (int half = 0; half < 2; ++half) {
            const size_t row = r_base + mt * 16 + half * 8;
            const float* ksrc = nullptr;
            const float* vsrc = nullptr;
            const float* qrow = nullptr;
            size_t grow = row;
            if (EPI == 2) {
                const size_t bq = row / 24;
                const int j = (int)(row % 24);
                const int b = (int)(bq >> 12);
                grow = bq * NB + j;
                if (j < KNN_K) {
                    const int pi = g_knn[bq * KNN_K + j];
                    const size_t o = ((size_t)(b * NPTS) + pi) * 256;
                    ksrc = g_kp + o; vsrc = g_vp + o;
                } else {
                    const size_t o = (bq * KG2 + (j - KNN_K)) * 256;
                    ksrc = g_gk + o; vsrc = g_gv + o;
                }
                qrow = g_qa + b * 256;
            }
#pragma unroll
            for (int nt = 0; nt < 4; ++nt) {
                const int col = c_base + nt * 8;
                float ox = acc[mt][nt][half * 2 + 0];
                float oy = acc[mt][nt][half * 2 + 1];
                if (bias) {
                    const float2 bv = *(const float2*)(bias + col);
                    ox += bv.x; oy += bv.y;
                }
                if (EPI == 0) {
                    *(float2*)(C + row * 256 + col) = make_float2(ox, oy);
                } else if (EPI == 1) {
                    ox = fmaxf(ox, 0.f); oy = fmaxf(oy, 0.f);
                    uint32_t h, l;
                    split2(ox, oy, h, l);
                    const int chunk = col >> 5, within = col & 31;
                    *(uint32_t*)(g_A1pack + pk_off(0, chunk, XROWS, row, within)) = h;
                    *(uint32_t*)(g_A1pack + pk_off(1, chunk, XROWS, row, within)) = l;
                } else {
                    const float2 kk = *(const float2*)(ksrc + col);
                    const float2 vv = *(const float2*)(vsrc + col);
                    const float2 qq = *(const float2*)(qrow + col);
                    const float xa = qq.x - kk.x + ox;
                    const float xb = qq.y - kk.y + oy;
                    uint32_t h, l;
                    split2(xa, xb, h, l);
                    const int chunk = col >> 5, within = col & 31;
                    *(uint32_t*)(g_Xpack + pk_off(0, chunk, XROWS, grow, within)) = h;
                    *(uint32_t*)(g_Xpack + pk_off(1, chunk, XROWS, grow, within)) = l;
                    *(float2*)(g_V + grow * 256 + col) = make_float2(vv.x + ox, vv.y + oy);
                }
            }
        }
    }
}

// ---------------- final: per-channel softmax over 25 neighbors, dot with V ------
__global__ __launch_bounds__(256)
void final_kernel(float* __restrict__ out) {
    const int bq = blockIdx.x;
    const int f  = threadIdx.x;
    const size_t base = (size_t)bq * NB * DIM + f;
    float a[NB];
#pragma unroll
    for (int j = 0; j < NB; ++j) a[j] = g_Xf[base + j * DIM];
    float m = a[0];
#pragma unroll
    for (int j = 1; j < NB; ++j) m = fmaxf(m, a[j]);
    float s = 0.f, o = 0.f;
#pragma unroll
    for (int j = 0; j < NB; ++j) {
        const float w = expf(a[j] - m);
        s += w;
        o = fmaf(w, g_V[base + j * DIM], o);
    }
    out[(size_t)bq * DIM + f] = o / s;
}

// ---------------- launch ----------------
extern "C" void kernel_launch(void* const* d_in, const int* in_sizes, int n_in,
                              void* d_out, int out_size) {
    const float* xyz_q  = (const float*)d_in[0];
    const float* lat    = (const float*)d_in[1];
    const float* xyz    = (const float*)d_in[2];
    const float* points = (const float*)d_in[3];
    const float* sgf    = (const float*)d_in[4];
    const float* closest= (const float*)d_in[5];
    const float* w_qs   = (const float*)d_in[6];
    const float* w_ks   = (const float*)d_in[7];
    const float* w_vs   = (const float*)d_in[8];
    const float* w_kc   = (const float*)d_in[9];
    const float* w_vc   = (const float*)d_in[10];
    const float* w_kg   = (const float*)d_in[11];
    const float* w_vg   = (const float*)d_in[12];
    const float* dw1    = (const float*)d_in[13];
    const float* db1    = (const float*)d_in[14];
    const float* dw2    = (const float*)d_in[15];
    const float* db2    = (const float*)d_in[16];
    const float* gw1    = (const float*)d_in[17];
    const float* gb1    = (const float*)d_in[18];
    const float* gw2    = (const float*)d_in[19];
    const float* gb2    = (const float*)d_in[20];

    float *kp, *vp, *gk, *gv, *Xf;
    char *Ppk, *Spk, *Xpk, *A1pk;
    cudaGetSymbolAddress((void**)&kp,   g_kp);
    cudaGetSymbolAddress((void**)&vp,   g_vp);
    cudaGetSymbolAddress((void**)&gk,   g_gk);
    cudaGetSymbolAddress((void**)&gv,   g_gv);
    cudaGetSymbolAddress((void**)&Xf,   g_Xf);
    cudaGetSymbolAddress((void**)&Ppk,  g_Ppack);
    cudaGetSymbolAddress((void**)&Spk,  g_Spack);
    cudaGetSymbolAddress((void**)&Xpk,  g_Xpack);
    cudaGetSymbolAddress((void**)&A1pk, g_A1pack);

    cudaFuncSetAttribute(gemm_cp_kernel<0, 0>, cudaFuncAttributeMaxDynamicSharedMemorySize, SMEM_DYN);
    cudaFuncSetAttribute(gemm_cp_kernel<0, 1>, cudaFuncAttributeMaxDynamicSharedMemorySize, SMEM_DYN);
    cudaFuncSetAttribute(gemm_cp_kernel<1, 2>, cudaFuncAttributeMaxDynamicSharedMemorySize, SMEM_DYN);

    // weight pack order: 0=w_ks 1=w_vs 2=w_kc 3=w_vc 4=dw2 5=gw1 6=gw2
    prepack_kernel<<<112, 256>>>(w_ks, w_vs, w_kc, w_vc, dw2, gw1, gw2);
    pack_a_kernel<<<(BATCH * NPTS) / 2, 256>>>(points, Ppk, BATCH * NPTS);
    pack_a_kernel<<<(BATCH * NQ * KG2) / 2, 256>>>(sgf, Spk, BATCH * NQ * KG2);

    knn_kernel<<<dim3(NQ / 16, BATCH), 256>>>(xyz_q, xyz);
    proj_small_kernel<<<BATCH, 256>>>(lat, w_qs, w_kg, w_vg);

    gemm_cp_kernel<0, 0><<<dim3((BATCH * NPTS) / 64, 2), 256, SMEM_DYN>>>(Ppk, BATCH * NPTS, 0, nullptr, kp, nullptr, nullptr);
    gemm_cp_kernel<0, 0><<<dim3((BATCH * NPTS) / 64, 2), 256, SMEM_DYN>>>(Ppk, BATCH * NPTS, 1, nullptr, vp, nullptr, nullptr);
    gemm_cp_kernel<0, 0><<<dim3((BATCH * NQ * KG2) / 64, 2), 256, SMEM_DYN>>>(Spk, BATCH * NQ * KG2, 2, nullptr, gk, nullptr, nullptr);
    gemm_cp_kernel<0, 0><<<dim3((BATCH * NQ * KG2) / 64, 2), 256, SMEM_DYN>>>(Spk, BATCH * NQ * KG2, 3, nullptr, gv, nullptr, nullptr);

    db_kernel<<<BATCH * NQ, 256>>>(xyz_q, xyz, closest);

    // pos GEMM: layer1 fused in producer; epilogue gathers k/v and writes X-pack + V
    gemm_cp_kernel<1, 2><<<dim3(POSROWS / 64, 2), 256, SMEM_DYN>>>(nullptr, POSROWS, 4, db2, nullptr, dw1, db1);

    // gamma MLP
    gemm_cp_kernel<0, 1><<<dim3(XROWS / 64, 2), 256, SMEM_DYN>>>(Xpk, XROWS, 5, gb1, nullptr, nullptr, nullptr);
    gemm_cp_kernel<0, 0><<<dim3(XROWS / 64, 2), 256, SMEM_DYN>>>(A1pk, XROWS, 6, gb2, Xf, nullptr, nullptr);

    final_kernel<<<BATCH * NQ, 256>>>((float*)d_out);
}

// round 15
// speedup vs baseline: 2.6320x; 1.1569x over previous
#include <cuda_runtime.h>
#include <cuda_bf16.h>
#include <cstdint>

// ---------------- problem constants ----------------
#define BATCH 2
#define NQ    4096
#define NPTS  8192
#define DIM   256
#define KNN_K 16
#define KG2   8
#define NB    25
#define XROWS 204800            // BATCH*NQ*NB
#define POSROWS 196608          // BATCH*NQ*24
#define FLT_BIG 3.402823466e+38f

// ---------------- scratch (device globals; no allocations) ----------------
__device__ float g_kp [BATCH * NPTS * DIM];
__device__ float g_vp [BATCH * NPTS * DIM];
__device__ float g_gk [BATCH * NQ * KG2 * DIM];
__device__ float g_gv [BATCH * NQ * KG2 * DIM];
__device__ float g_qa [BATCH * DIM];
__device__ float g_kgl[BATCH * DIM];
__device__ float g_vgl[BATCH * DIM];
__device__ int   g_knn[BATCH * NQ * KNN_K];
__device__ float g_db [BATCH * NQ * 24 * 4];
__device__ float g_V  [(size_t)XROWS * DIM];
__device__ float g_Xf [(size_t)XROWS * DIM];     // gamma2 output (logits)
// packed bf16 hi/lo A-operand planes: layout ((plane*8 + chunk)*Mtot + row)*80 + (col%32)*2
__device__ char  g_Xpack [(size_t)2 * 8 * XROWS * 80];
__device__ char  g_A1pack[(size_t)2 * 8 * XROWS * 80];
__device__ char  g_Ppack [(size_t)2 * 8 * (BATCH * NPTS) * 80];
__device__ char  g_Spack [(size_t)2 * 8 * (BATCH * NQ * KG2) * 80];
// prepacked weights: 7 weights x 8 k-chunks x 2 n-blocks, each region =
// [hi: 128 n-rows x 40 bf16][lo: same] = 20480 B
__device__ uint4 g_Bpack[7 * 8 * 2 * 1280];

// ---------------- PTX helpers (portable, no 'a'-gated features) ----------------
#define LDM_X4(r0, r1, r2, r3, addr) \
    asm volatile("ldmatrix.sync.aligned.m8n8.x4.shared.b16 {%0,%1,%2,%3}, [%4];" \
        : "=r"(r0), "=r"(r1), "=r"(r2), "=r"(r3) : "r"(addr))

#define MMA16816(d, a, b) \
    asm volatile("mma.sync.aligned.m16n8k16.row.col.f32.bf16.bf16.f32 " \
        "{%0,%1,%2,%3}, {%4,%5,%6,%7}, {%8,%9}, {%0,%1,%2,%3};" \
        : "+f"((d)[0]), "+f"((d)[1]), "+f"((d)[2]), "+f"((d)[3]) \
        : "r"((a)[0]), "r"((a)[1]), "r"((a)[2]), "r"((a)[3]), \
          "r"((b)[0]), "r"((b)[1]))

#define CP_ASYNC16(dst, src) \
    asm volatile("cp.async.cg.shared.global [%0], [%1], 16;" :: "r"(dst), "l"(src))
#define CP_COMMIT() asm volatile("cp.async.commit_group;" ::: "memory")
#define CP_WAIT1()  asm volatile("cp.async.wait_group 1;" ::: "memory")
#define CP_WAIT0()  asm volatile("cp.async.wait_group 0;" ::: "memory")

__device__ __forceinline__ uint32_t smem_u32(const void* p) {
    uint32_t a;
    asm("{ .reg .u64 t; cvta.to.shared.u64 t, %1; cvt.u32.u64 %0, t; }" : "=r"(a) : "l"(p));
    return a;
}

// two fp32 -> packed bf16 hi pair + lo (residual) pair
__device__ __forceinline__ void split2(float a, float b, uint32_t& h, uint32_t& l) {
    __nv_bfloat16 ha = __float2bfloat16(a), hb = __float2bfloat16(b);
    float ra = a - __bfloat162float(ha);
    float rb = b - __bfloat162float(hb);
    h = (uint32_t)__bfloat16_as_ushort(ha) | ((uint32_t)__bfloat16_as_ushort(hb) << 16);
    __nv_bfloat16 la = __float2bfloat16(ra), lb = __float2bfloat16(rb);
    l = (uint32_t)__bfloat16_as_ushort(la) | ((uint32_t)__bfloat16_as_ushort(lb) << 16);
}

// packed-plane byte offset
__device__ __forceinline__ size_t pk_off(int plane, int chunk, size_t Mtot, size_t row, int within) {
    return ((size_t)(plane * 8 + chunk) * Mtot + row) * 80 + (size_t)within * 2;
}

// SMEM stage layout (bytes): [A_hi 5120][A_lo 5120][B_hi 10240][B_lo 10240]
#define STG   30720
#define SA_LO 5120
#define SB_HI 10240
#define SMEM_DYN (3 * STG)

// ---------------- KNN: warp-cooperative, one warp per query ----------------
// Top-32 (d,idx) list lives distributed across the warp's 32 lanes, sorted
// lexicographically ascending on (d, idx). Candidates are inserted in
// ascending global index order, so the first 16 lanes at the end are EXACTLY
// the stable top-16 (matches jax.lax.top_k tie semantics).
__global__ __launch_bounds__(256)
void knn_kernel(const float* __restrict__ xyz_q, const float* __restrict__ xyz) {
    const int b    = blockIdx.y;
    const int tid  = threadIdx.x;
    const int lane = tid & 31;
    const int w    = tid >> 5;                 // warp = query within block
    const int q    = blockIdx.x * 8 + w;

    __shared__ float4 sp[1024];

    const size_t qb = (size_t)(b * NQ + q) * 3;
    const float qx = xyz_q[qb + 0], qy = xyz_q[qb + 1], qz = xyz_q[qb + 2];
    const float qq = qx * qx + qy * qy + qz * qz;

    float vd = FLT_BIG;          // this lane's slot of the sorted top-32 list
    int   vi = 0x7fffffff;
    float maxd = FLT_BIG;        // lane-31 (worst) entry, replicated
    int   maxi = 0x7fffffff;

    for (int tile = 0; tile < 8; ++tile) {
        const int t0 = tile * 1024;
        __syncthreads();
        for (int i = tid; i < 1024; i += 256) {
            const size_t pb = (size_t)(b * NPTS + t0 + i) * 3;
            float x = xyz[pb + 0], y = xyz[pb + 1], z = xyz[pb + 2];
            sp[i] = make_float4(x, y, z, x * x + y * y + z * z);
        }
        __syncthreads();
        for (int i = 0; i < 1024; i += 32) {
            const float4 P = sp[i + lane];
            const float dot = qx * P.x + qy * P.y + qz * P.z;
            const float d2  = (qq + P.w) - 2.0f * dot;
            const int   ci  = t0 + i + lane;
            const bool pass = (d2 < maxd) || (d2 == maxd && ci < maxi);
            unsigned m = __ballot_sync(0xffffffffu, pass);
            while (m) {
                const int src = __ffs(m) - 1;   // lowest lane first = ascending index
                m &= m - 1;
                const float dn = __shfl_sync(0xffffffffu, d2, src);
                const int   in = __shfl_sync(0xffffffffu, ci, src);
                // list may have tightened during earlier inserts this iteration
                if (dn < maxd || (dn == maxd && in < maxi)) {
                    const float sdv = __shfl_up_sync(0xffffffffu, vd, 1);
                    const int   siv = __shfl_up_sync(0xffffffffu, vi, 1);
                    const bool gt = (dn < vd) || (dn == vd && in < vi);
                    const unsigned bb = __ballot_sync(0xffffffffu, gt);
                    const int pos = __ffs(bb) - 1;   // bb != 0 (lane 31 passes)
                    if (gt) {
                        vd = (lane == pos) ? dn : sdv;
                        vi = (lane == pos) ? in : siv;
                    }
                    maxd = __shfl_sync(0xffffffffu, vd, 31);
                    maxi = __shfl_sync(0xffffffffu, vi, 31);
                }
            }
        }
    }
    if (lane < KNN_K)
        g_knn[(size_t)(b * NQ + q) * KNN_K + lane] = vi;
}

// ---------------- tiny projections ----------------
__global__ __launch_bounds__(256)
void proj_small_kernel(const float* __restrict__ lat,
                       const float* __restrict__ w_qs,
                       const float* __restrict__ w_kg,
                       const float* __restrict__ w_vg) {
    const int b = blockIdx.x, t = threadIdx.x;
    __shared__ float ls[DIM];
    ls[t] = lat[b * DIM + t];
    __syncthreads();
    float aq = 0.f, ak = 0.f, av = 0.f;
    for (int i = 0; i < DIM; ++i) {
        const float l = ls[i];
        aq = fmaf(l, w_qs[i * DIM + t], aq);
        ak = fmaf(l, w_kg[i * DIM + t], ak);
        av = fmaf(l, w_vg[i * DIM + t], av);
    }
    g_qa [b * DIM + t] = aq;
    g_kgl[b * DIM + t] = ak;
    g_vgl[b * DIM + t] = av;
}

// ---------------- weight prepack (unchanged layout) ----------------
__global__ __launch_bounds__(256)
void prepack_kernel(const float* __restrict__ w0, const float* __restrict__ w1,
                    const float* __restrict__ w2, const float* __restrict__ w3,
                    const float* __restrict__ w4, const float* __restrict__ w5,
                    const float* __restrict__ w6) {
    const float* Ws[7] = {w0, w1, w2, w3, w4, w5, w6};
    const int bid = blockIdx.x;
    const int w = bid >> 4, kc = (bid >> 1) & 7, nblk = bid & 1;
    const float* W = Ws[w];
    char* dst = (char*)g_Bpack + (size_t)bid * 20480;
#pragma unroll
    for (int i = 0; i < 16; ++i) {
        const int idx = threadIdx.x + i * 256;
        const int n_local = idx >> 5, k_local = idx & 31;
        const int n = nblk * 128 + n_local;
        const int k = kc * 32 + k_local;
        const float x = W[(size_t)k * 256 + n];
        __nv_bfloat16 h = __float2bfloat16(x);
        float lo = x - __bfloat162float(h);
        *(__nv_bfloat16*)(dst + n_local * 80 + k_local * 2)         = h;
        *(__nv_bfloat16*)(dst + 10240 + n_local * 80 + k_local * 2) = __float2bfloat16(lo);
    }
}

// ---------------- A prepack: fp32 [M,256] -> hi/lo plane format ----------------
__global__ __launch_bounds__(256)
void pack_a_kernel(const float* __restrict__ A, char* __restrict__ dst, int Mtot) {
    const size_t row = (size_t)blockIdx.x * 2 + (threadIdx.x >> 7);
    const int cp = threadIdx.x & 127;
    const int col = cp * 2;
    const float2 v = *(const float2*)(A + row * 256 + col);
    uint32_t h, l;
    split2(v.x, v.y, h, l);
    const int chunk = col >> 5, within = col & 31;
    *(uint32_t*)(dst + pk_off(0, chunk, (size_t)Mtot, row, within)) = h;
    *(uint32_t*)(dst + pk_off(1, chunk, (size_t)Mtot, row, within)) = l;
}

// ---------------- db + global-token row24 ----------------
__global__ __launch_bounds__(256)
void db_kernel(const float* __restrict__ xyz_q,
               const float* __restrict__ xyz,
               const float* __restrict__ closest) {
    const int bq = blockIdx.x;
    const int b  = bq >> 12;
    const int t  = threadIdx.x;
    __shared__ int   knn_s[KNN_K];
    __shared__ float q3[3];
    if (t < KNN_K) knn_s[t] = g_knn[(size_t)bq * KNN_K + t];
    if (t < 3)     q3[t]    = xyz_q[(size_t)bq * 3 + t];
    __syncthreads();

    if (t < 72) {
        const int j = t / 3, d = t % 3;
        float src;
        if (j < KNN_K) src = xyz[(size_t)(b * NPTS + knn_s[j]) * 3 + d];
        else           src = closest[((size_t)bq * KG2 + (j - KNN_K)) * 3 + d];
        g_db[(size_t)(bq * 24 + j) * 4 + d] = q3[d] - src;
    }
    // global token: X row24 packed = qa - kgl, V row24 = vgl
    const size_t grow = (size_t)bq * NB + 24;
    if (t < 128) {
        const int col = t * 2;
        const float2 qa2 = *(const float2*)(g_qa  + b * 256 + col);
        const float2 kg2 = *(const float2*)(g_kgl + b * 256 + col);
        uint32_t h, l;
        split2(qa2.x - kg2.x, qa2.y - kg2.y, h, l);
        const int chunk = col >> 5, within = col & 31;
        *(uint32_t*)(g_Xpack + pk_off(0, chunk, XROWS, grow, within)) = h;
        *(uint32_t*)(g_Xpack + pk_off(1, chunk, XROWS, grow, within)) = l;
    }
    g_V[grow * 256 + t] = g_vgl[b * 256 + t];
}

// ---------------- cp.async mma GEMM: C[M x 256] = A @ W (bf16x3) ----------------
// CTA tile M64 x N128 (blockIdx.y = n-half), 8 warps 2(m) x 4(n), K chunk 32, 3 stages.
// ASRC 0: A from packed planes (pure cp.async).  ASRC 1: A = relu(d @ W1 + b1) from g_db.
// EPI 0: C = acc (+bias) fp32.  EPI 1: relu + write packed A1.  EPI 2: pos gather -> X packed + V.
template<int ASRC, int EPI>
__global__ __launch_bounds__(256, 2)
void gemm_cp_kernel(const char* __restrict__ Apack, size_t Mtot, int widx,
                    const float* __restrict__ bias, float* __restrict__ C,
                    const float* __restrict__ W1, const float* __restrict__ b1) {
    extern __shared__ char smem_dyn[];
    const uint32_t sb0 = smem_u32(smem_dyn);
    const int tid = threadIdx.x, lane = tid & 31, wid = tid >> 5;
    const int warp_n = wid & 3, warp_m = wid >> 2;
    const size_t m0 = (size_t)blockIdx.x * 64;
    const int n0 = blockIdx.y * 128;

    const char* bbase = (const char*)g_Bpack + ((size_t)(widx * 8) * 2 + blockIdx.y) * 20480;

    float acc[2][4][4];
#pragma unroll
    for (int mt = 0; mt < 2; ++mt)
#pragma unroll
        for (int nt = 0; nt < 4; ++nt)
#pragma unroll
            for (int j = 0; j < 4; ++j) acc[mt][nt][j] = 0.f;

    // DB producer state
    const int arow = tid >> 2, kq = (tid & 3) * 8;
    float4 dd;
    if (ASRC == 1) dd = *(const float4*)(g_db + (m0 + arow) * 4);

    // ---- issue helpers ----
#define ISSUE_CHUNK(c_, buf_) do {                                              \
        const char* bsrc_ = bbase + (size_t)(c_) * 40960;                       \
        const uint32_t bdst_ = sb0 + (buf_) * STG + SB_HI;                      \
        _Pragma("unroll")                                                       \
        for (int i_ = tid; i_ < 1280; i_ += 256)                                \
            CP_ASYNC16(bdst_ + i_ * 16, bsrc_ + (size_t)i_ * 16);               \
        if (ASRC == 0) {                                                        \
            _Pragma("unroll")                                                   \
            for (int i_ = tid; i_ < 640; i_ += 256) {                           \
                const int p_ = i_ / 320, l_ = i_ - p_ * 320;                    \
                const char* asrc_ = Apack +                                     \
                    ((size_t)(p_ * 8 + (c_)) * Mtot + m0) * 80 + (size_t)l_ * 16; \
                CP_ASYNC16(sb0 + (buf_) * STG + p_ * SA_LO + l_ * 16, asrc_);   \
            }                                                                   \
        }                                                                       \
        CP_COMMIT();                                                            \
    } while (0)

    ISSUE_CHUNK(0, 0);
    ISSUE_CHUNK(1, 1);

    for (int c = 0; c < 8; ++c) {
        const int buf = c % 3;
        if (c < 6) CP_WAIT1(); else CP_WAIT0();
        __syncthreads();
        if (c + 2 < 8) ISSUE_CHUNK(c + 2, (c + 2) % 3);

        if (ASRC == 1) {
            float v[8];
#pragma unroll
            for (int i = 0; i < 8; ++i) {
                const int k = c * 32 + kq + i;
                float h = fmaf(dd.x, W1[k], fmaf(dd.y, W1[256 + k], fmaf(dd.z, W1[512 + k], b1[k])));
                v[i] = fmaxf(h, 0.f);
            }
            uint4 h0, l0;
            split2(v[0], v[1], h0.x, l0.x); split2(v[2], v[3], h0.y, l0.y);
            split2(v[4], v[5], h0.z, l0.z); split2(v[6], v[7], h0.w, l0.w);
            char* stc = smem_dyn + buf * STG;
            *(uint4*)(stc + arow * 80 + kq * 2)         = h0;
            *(uint4*)(stc + SA_LO + arow * 80 + kq * 2) = l0;
            __syncthreads();
        }

        const uint32_t sb = sb0 + buf * STG;
#pragma unroll
        for (int ks = 0; ks < 2; ++ks) {
            uint32_t ah[2][4], al[2][4];
#pragma unroll
            for (int mt = 0; mt < 2; ++mt) {
                const uint32_t ra = sb + (uint32_t)(warp_m * 32 + mt * 16 + (lane & 15)) * 80
                                  + ks * 32 + ((lane >> 4) << 4);
                LDM_X4(ah[mt][0], ah[mt][1], ah[mt][2], ah[mt][3], ra);
                LDM_X4(al[mt][0], al[mt][1], al[mt][2], al[mt][3], ra + SA_LO);
            }
            uint32_t bh[4][2], bl[4][2];
#pragma unroll
            for (int np = 0; np < 2; ++np) {
                const uint32_t rb = sb + SB_HI
                                  + (uint32_t)(warp_n * 32 + np * 16 + (lane & 7) + ((lane >> 4) << 3)) * 80
                                  + ks * 32 + ((lane & 8) ? 16 : 0);
                LDM_X4(bh[2 * np][0], bh[2 * np][1], bh[2 * np + 1][0], bh[2 * np + 1][1], rb);
                LDM_X4(bl[2 * np][0], bl[2 * np][1], bl[2 * np + 1][0], bl[2 * np + 1][1], rb + 10240);
            }
#pragma unroll
            for (int mt = 0; mt < 2; ++mt)
#pragma unroll
                for (int nt = 0; nt < 4; ++nt) {
                    MMA16816(acc[mt][nt], ah[mt], bh[nt]);
                    MMA16816(acc[mt][nt], ah[mt], bl[nt]);
                    MMA16816(acc[mt][nt], al[mt], bh[nt]);
                }
        }
    }
#undef ISSUE_CHUNK

    // ---- epilogue ----
    const size_t r_base = m0 + warp_m * 32 + (lane >> 2);
    const int c_base = n0 + warp_n * 32 + (lane & 3) * 2;
#pragma unroll
    for (int mt = 0; mt < 2; ++mt) {
#pragma unroll
        for (int half = 0; half < 2; ++half) {
            const size_t row = r_base + mt * 16 + half * 8;
            const float* ksrc = nullptr;
            const float* vsrc = nullptr;
            const float* qrow = nullptr;
            size_t grow = row;
            if (EPI == 2) {
                const size_t bq = row / 24;
                const int j = (int)(row % 24);
                const int b = (int)(bq >> 12);
                grow = bq * NB + j;
                if (j < KNN_K) {
                    const int pi = g_knn[bq * KNN_K + j];
                    const size_t o = ((size_t)(b * NPTS) + pi) * 256;
                    ksrc = g_kp + o; vsrc = g_vp + o;
                } else {
                    const size_t o = (bq * KG2 + (j - KNN_K)) * 256;
                    ksrc = g_gk + o; vsrc = g_gv + o;
                }
                qrow = g_qa + b * 256;
            }
#pragma unroll
            for (int nt = 0; nt < 4; ++nt) {
                const int col = c_base + nt * 8;
                float ox = acc[mt][nt][half * 2 + 0];
                float oy = acc[mt][nt][half * 2 + 1];
                if (bias) {
                    const float2 bv = *(const float2*)(bias + col);
                    ox += bv.x; oy += bv.y;
                }
                if (EPI == 0) {
                    *(float2*)(C + row * 256 + col) = make_float2(ox, oy);
                } else if (EPI == 1) {
                    ox = fmaxf(ox, 0.f); oy = fmaxf(oy, 0.f);
                    uint32_t h, l;
                    split2(ox, oy, h, l);
                    const int chunk = col >> 5, within = col & 31;
                    *(uint32_t*)(g_A1pack + pk_off(0, chunk, XROWS, row, within)) = h;
                    *(uint32_t*)(g_A1pack + pk_off(1, chunk, XROWS, row, within)) = l;
                } else {
                    const float2 kk = *(const float2*)(ksrc + col);
                    const float2 vv = *(const float2*)(vsrc + col);
                    const float2 qq = *(const float2*)(qrow + col);
                    const float xa = qq.x - kk.x + ox;
                    const float xb = qq.y - kk.y + oy;
                    uint32_t h, l;
                    split2(xa, xb, h, l);
                    const int chunk = col >> 5, within = col & 31;
                    *(uint32_t*)(g_Xpack + pk_off(0, chunk, XROWS, grow, within)) = h;
                    *(uint32_t*)(g_Xpack + pk_off(1, chunk, XROWS, grow, within)) = l;
                    *(float2*)(g_V + grow * 256 + col) = make_float2(vv.x + ox, vv.y + oy);
                }
            }
        }
    }
}

// ---------------- final: per-channel softmax over 25 neighbors, dot with V ------
__global__ __launch_bounds__(256)
void final_kernel(float* __restrict__ out) {
    const int bq = blockIdx.x;
    const int f  = threadIdx.x;
    const size_t base = (size_t)bq * NB * DIM + f;
    float a[NB];
#pragma unroll
    for (int j = 0; j < NB; ++j) a[j] = g_Xf[base + j * DIM];
    float m = a[0];
#pragma unroll
    for (int j = 1; j < NB; ++j) m = fmaxf(m, a[j]);
    float s = 0.f, o = 0.f;
#pragma unroll
    for (int j = 0; j < NB; ++j) {
        const float w = expf(a[j] - m);
        s += w;
        o = fmaf(w, g_V[base + j * DIM], o);
    }
    out[(size_t)bq * DIM + f] = o / s;
}

// ---------------- launch ----------------
extern "C" void kernel_launch(void* const* d_in, const int* in_sizes, int n_in,
                              void* d_out, int out_size) {
    const float* xyz_q  = (const float*)d_in[0];
    const float* lat    = (const float*)d_in[1];
    const float* xyz    = (const float*)d_in[2];
    const float* points = (const float*)d_in[3];
    const float* sgf    = (const float*)d_in[4];
    const float* closest= (const float*)d_in[5];
    const float* w_qs   = (const float*)d_in[6];
    const float* w_ks   = (const float*)d_in[7];
    const float* w_vs   = (const float*)d_in[8];
    const float* w_kc   = (const float*)d_in[9];
    const float* w_vc   = (const float*)d_in[10];
    const float* w_kg   = (const float*)d_in[11];
    const float* w_vg   = (const float*)d_in[12];
    const float* dw1    = (const float*)d_in[13];
    const float* db1    = (const float*)d_in[14];
    const float* dw2    = (const float*)d_in[15];
    const float* db2    = (const float*)d_in[16];
    const float* gw1    = (const float*)d_in[17];
    const float* gb1    = (const float*)d_in[18];
    const float* gw2    = (const float*)d_in[19];
    const float* gb2    = (const float*)d_in[20];

    float *kp, *vp, *gk, *gv, *Xf;
    char *Ppk, *Spk, *Xpk, *A1pk;
    cudaGetSymbolAddress((void**)&kp,   g_kp);
    cudaGetSymbolAddress((void**)&vp,   g_vp);
    cudaGetSymbolAddress((void**)&gk,   g_gk);
    cudaGetSymbolAddress((void**)&gv,   g_gv);
    cudaGetSymbolAddress((void**)&Xf,   g_Xf);
    cudaGetSymbolAddress((void**)&Ppk,  g_Ppack);
    cudaGetSymbolAddress((void**)&Spk,  g_Spack);
    cudaGetSymbolAddress((void**)&Xpk,  g_Xpack);
    cudaGetSymbolAddress((void**)&A1pk, g_A1pack);

    cudaFuncSetAttribute(gemm_cp_kernel<0, 0>, cudaFuncAttributeMaxDynamicSharedMemorySize, SMEM_DYN);
    cudaFuncSetAttribute(gemm_cp_kernel<0, 1>, cudaFuncAttributeMaxDynamicSharedMemorySize, SMEM_DYN);
    cudaFuncSetAttribute(gemm_cp_kernel<1, 2>, cudaFuncAttributeMaxDynamicSharedMemorySize, SMEM_DYN);

    // weight pack order: 0=w_ks 1=w_vs 2=w_kc 3=w_vc 4=dw2 5=gw1 6=gw2
    prepack_kernel<<<112, 256>>>(w_ks, w_vs, w_kc, w_vc, dw2, gw1, gw2);
    pack_a_kernel<<<(BATCH * NPTS) / 2, 256>>>(points, Ppk, BATCH * NPTS);
    pack_a_kernel<<<(BATCH * NQ * KG2) / 2, 256>>>(sgf, Spk, BATCH * NQ * KG2);

    knn_kernel<<<dim3(NQ / 8, BATCH), 256>>>(xyz_q, xyz);
    proj_small_kernel<<<BATCH, 256>>>(lat, w_qs, w_kg, w_vg);

    gemm_cp_kernel<0, 0><<<dim3((BATCH * NPTS) / 64, 2), 256, SMEM_DYN>>>(Ppk, BATCH * NPTS, 0, nullptr, kp, nullptr, nullptr);
    gemm_cp_kernel<0, 0><<<dim3((BATCH * NPTS) / 64, 2), 256, SMEM_DYN>>>(Ppk, BATCH * NPTS, 1, nullptr, vp, nullptr, nullptr);
    gemm_cp_kernel<0, 0><<<dim3((BATCH * NQ * KG2) / 64, 2), 256, SMEM_DYN>>>(Spk, BATCH * NQ * KG2, 2, nullptr, gk, nullptr, nullptr);
    gemm_cp_kernel<0, 0><<<dim3((BATCH * NQ * KG2) / 64, 2), 256, SMEM_DYN>>>(Spk, BATCH * NQ * KG2, 3, nullptr, gv, nullptr, nullptr);

    db_kernel<<<BATCH * NQ, 256>>>(xyz_q, xyz, closest);

    // pos GEMM: layer1 fused in producer; epilogue gathers k/v and writes X-pack + V
    gemm_cp_kernel<1, 2><<<dim3(POSROWS / 64, 2), 256, SMEM_DYN>>>(nullptr, POSROWS, 4, db2, nullptr, dw1, db1);

    // gamma MLP
    gemm_cp_kernel<0, 1><<<dim3(XROWS / 64, 2), 256, SMEM_DYN>>>(Xpk, XROWS, 5, gb1, nullptr, nullptr, nullptr);
    gemm_cp_kernel<0, 0><<<dim3(XROWS / 64, 2), 256, SMEM_DYN>>>(A1pk, XROWS, 6, gb2, Xf, nullptr, nullptr);

    final_kernel<<<BATCH * NQ, 256>>>((float*)d_out);
}